// round 1
// baseline (speedup 1.0000x reference)
#include <cuda_runtime.h>
#include <cuda_bf16.h>
#include <math.h>
#include <stdint.h>

// ---------------------------------------------------------------------------
// TGAN: 2-layer graph transformer with edge-bias attention.
// B=64 batch, N=64 nodes, D=128, NH=2 heads (d_k=128 each), L=2 layers.
// Output: [B,D] mean-pooled emb (8192 f32) followed by attn [L,NH,B,N,N].
// ---------------------------------------------------------------------------

#define Bb 64
#define Nn 64
#define Dm 128
#define NHh 2
#define Ll 2
#define ROWS (Bb*Nn)          // 4096
#define EDGE_M (Bb*Nn*Nn)     // 262144

// ------------------------- scratch (device globals) ------------------------
__device__ float g_emb [ROWS*Dm];          // [B*N,128]
__device__ float g_h   [ROWS*Dm];          // LN output
__device__ float g_q   [ROWS*2*Dm];        // [B*N,256]
__device__ float g_k   [ROWS*2*Dm];
__device__ float g_v   [ROWS*2*Dm];
__device__ float g_att [ROWS*2*Dm];        // MHA concat output [B*N,256]
__device__ float g_mid [ROWS*4*Dm];        // FFN mid [B*N,512]
__device__ float g_bias[(size_t)EDGE_M*Dm];// edge bias [B,N,N,128]  (134 MB)
__device__ int   g_mask_mode;              // 0=int32, 1=float32, 2=byte

// ------------------------- mask dtype autodetect ---------------------------
// mask has 262144 elements; smallest possible buffer = 262144 bytes = 65536
// 32-bit words, so scanning 65536 words is always in-bounds.
__global__ void detect_mask_kernel(const unsigned int* __restrict__ m) {
    __shared__ int s_flags;
    if (threadIdx.x == 0) s_flags = 0;
    __syncthreads();
    int f = 0;
    for (int p = threadIdx.x; p < 65536; p += blockDim.x) {
        unsigned w = m[p];
        if (w > 1u) f |= 1;                          // not plain int32 0/1
        if (w != 0u && w != 0x3F800000u) f |= 2;     // not float32 0.0/1.0
    }
    if (f) atomicOr(&s_flags, f);
    __syncthreads();
    if (threadIdx.x == 0) {
        int fl = s_flags;
        g_mask_mode = (!(fl & 1)) ? 0 : ((!(fl & 2)) ? 1 : 2);
    }
}

__device__ __forceinline__ bool mask_at(const void* m, int idx, int mode) {
    if (mode == 0) return ((const int*)m)[idx] != 0;
    if (mode == 1) return ((const float*)m)[idx] != 0.0f;
    return ((const unsigned char*)m)[idx] != 0;
}

// ------------------------- LayerNorm (row = 128) ---------------------------
__global__ __launch_bounds__(128) void ln_kernel(
    const float* __restrict__ x, const float* __restrict__ g,
    const float* __restrict__ b, float* __restrict__ y, float eps)
{
    int row = blockIdx.x, t = threadIdx.x;
    float v = x[(size_t)row*Dm + t];
    float s = v;
    #pragma unroll
    for (int o = 16; o; o >>= 1) s += __shfl_xor_sync(0xffffffffu, s, o);
    __shared__ float red[8];
    if ((t & 31) == 0) red[t >> 5] = s;
    __syncthreads();
    float mean = (red[0] + red[1] + red[2] + red[3]) * (1.0f / 128.0f);
    float d = v - mean;
    float q = d * d;
    #pragma unroll
    for (int o = 16; o; o >>= 1) q += __shfl_xor_sync(0xffffffffu, q, o);
    if ((t & 31) == 0) red[4 + (t >> 5)] = q;
    __syncthreads();
    float var = (red[4] + red[5] + red[6] + red[7]) * (1.0f / 128.0f);
    y[(size_t)row*Dm + t] = d * rsqrtf(var + eps) * g[t] + b[t];
}

// ------------------------- generic small SGEMM -----------------------------
// C[M,N] = A[M,K] @ W[K,N] (+bias) (+res) (relu).  BM=BN=64, 256 thr, 4x4.
__global__ __launch_bounds__(256) void gemm64(
    const float* __restrict__ A, const float* __restrict__ W,
    const float* __restrict__ bias, const float* res, float* C,
    int M, int N, int K, int relu)
{
    __shared__ __align__(16) float AsT[16][68];
    __shared__ __align__(16) float Ws [16][64];
    const int m0 = blockIdx.x * 64, n0 = blockIdx.y * 64;
    const int t = threadIdx.x;
    const int lm = t >> 2, lk = (t & 3) * 4;      // A loader
    const int wk = t >> 4, wn = (t & 15) * 4;     // W loader
    const int tmi = t >> 4, tni = t & 15;         // compute

    float acc[4][4];
    #pragma unroll
    for (int i = 0; i < 4; i++)
        #pragma unroll
        for (int j = 0; j < 4; j++) acc[i][j] = 0.0f;

    for (int k0 = 0; k0 < K; k0 += 16) {
        float4 a = *(const float4*)&A[(size_t)(m0 + lm) * K + k0 + lk];
        float4 w = *(const float4*)&W[(size_t)(k0 + wk) * N + n0 + wn];
        __syncthreads();
        AsT[lk+0][lm] = a.x; AsT[lk+1][lm] = a.y;
        AsT[lk+2][lm] = a.z; AsT[lk+3][lm] = a.w;
        *(float4*)&Ws[wk][wn] = w;
        __syncthreads();
        #pragma unroll
        for (int kk = 0; kk < 16; kk++) {
            float4 av = *(const float4*)&AsT[kk][tmi * 4];
            float4 wv = *(const float4*)&Ws [kk][tni * 4];
            float aa[4] = {av.x, av.y, av.z, av.w};
            float ww[4] = {wv.x, wv.y, wv.z, wv.w};
            #pragma unroll
            for (int i = 0; i < 4; i++)
                #pragma unroll
                for (int j = 0; j < 4; j++) acc[i][j] += aa[i] * ww[j];
        }
    }

    float bv[4] = {0, 0, 0, 0};
    if (bias) {
        float4 b4 = *(const float4*)&bias[n0 + tni * 4];
        bv[0] = b4.x; bv[1] = b4.y; bv[2] = b4.z; bv[3] = b4.w;
    }
    #pragma unroll
    for (int i = 0; i < 4; i++) {
        size_t row = (size_t)(m0 + tmi * 4 + i);
        float o[4];
        #pragma unroll
        for (int j = 0; j < 4; j++) o[j] = acc[i][j] + bv[j];
        if (res) {
            float4 r = *(const float4*)&res[row * N + n0 + tni * 4];
            o[0] += r.x; o[1] += r.y; o[2] += r.z; o[3] += r.w;
        }
        if (relu) {
            #pragma unroll
            for (int j = 0; j < 4; j++) o[j] = fmaxf(o[j], 0.0f);
        }
        float4 st; st.x = o[0]; st.y = o[1]; st.z = o[2]; st.w = o[3];
        *(float4*)&C[row * N + n0 + tni * 4] = st;
    }
}

// ------------------------- bias SGEMM (M=262144, N=K=128) ------------------
// BM=128, BN=128 (full N), 256 threads, 8x8 micro-tile.
__global__ __launch_bounds__(256) void gemm128(
    const float* __restrict__ A, const float* __restrict__ W,
    const float* __restrict__ bias, float* __restrict__ C)
{
    __shared__ __align__(16) float AsT[16][132];
    __shared__ __align__(16) float Ws [16][128];
    const size_t m0 = (size_t)blockIdx.x * 128;
    const int t = threadIdx.x;
    const int lm = t >> 1, lk = (t & 1) * 8;      // A loader
    const int kr0 = t >> 5, nq0 = t & 31;         // W loader
    const int tmi = t >> 4, tni = t & 15;         // compute
    const float4* W4 = (const float4*)W;
    float4* Ws4 = (float4*)Ws;

    float acc[8][8];
    #pragma unroll
    for (int i = 0; i < 8; i++)
        #pragma unroll
        for (int j = 0; j < 8; j++) acc[i][j] = 0.0f;

    for (int k0 = 0; k0 < 128; k0 += 16) {
        float4 a0 = *(const float4*)&A[(m0 + lm) * 128 + k0 + lk];
        float4 a1 = *(const float4*)&A[(m0 + lm) * 128 + k0 + lk + 4];
        float4 w0 = W4[(size_t)(k0 + kr0)     * 32 + nq0];
        float4 w1 = W4[(size_t)(k0 + kr0 + 8) * 32 + nq0];
        __syncthreads();
        AsT[lk+0][lm] = a0.x; AsT[lk+1][lm] = a0.y;
        AsT[lk+2][lm] = a0.z; AsT[lk+3][lm] = a0.w;
        AsT[lk+4][lm] = a1.x; AsT[lk+5][lm] = a1.y;
        AsT[lk+6][lm] = a1.z; AsT[lk+7][lm] = a1.w;
        Ws4[kr0 * 32 + nq0]       = w0;
        Ws4[(kr0 + 8) * 32 + nq0] = w1;
        __syncthreads();
        #pragma unroll
        for (int kk = 0; kk < 16; kk++) {
            float4 x0 = *(const float4*)&AsT[kk][tmi * 8];
            float4 x1 = *(const float4*)&AsT[kk][tmi * 8 + 4];
            float4 y0 = Ws4[kk * 32 + tni * 2];
            float4 y1 = Ws4[kk * 32 + tni * 2 + 1];
            float av[8] = {x0.x, x0.y, x0.z, x0.w, x1.x, x1.y, x1.z, x1.w};
            float wv[8] = {y0.x, y0.y, y0.z, y0.w, y1.x, y1.y, y1.z, y1.w};
            #pragma unroll
            for (int i = 0; i < 8; i++)
                #pragma unroll
                for (int j = 0; j < 8; j++) acc[i][j] += av[i] * wv[j];
        }
    }

    float4 b0 = *(const float4*)&bias[tni * 8];
    float4 b1 = *(const float4*)&bias[tni * 8 + 4];
    float bv[8] = {b0.x, b0.y, b0.z, b0.w, b1.x, b1.y, b1.z, b1.w};
    #pragma unroll
    for (int r = 0; r < 8; r++) {
        size_t row = m0 + tmi * 8 + r;
        float4 o0, o1;
        o0.x = acc[r][0] + bv[0]; o0.y = acc[r][1] + bv[1];
        o0.z = acc[r][2] + bv[2]; o0.w = acc[r][3] + bv[3];
        o1.x = acc[r][4] + bv[4]; o1.y = acc[r][5] + bv[5];
        o1.z = acc[r][6] + bv[6]; o1.w = acc[r][7] + bv[7];
        *(float4*)&C[row * 128 + tni * 8]     = o0;
        *(float4*)&C[row * 128 + tni * 8 + 4] = o1;
    }
}

// ------------------------- fused attention ---------------------------------
// Per block: one batch b, TI query rows. SMEM holds K^T (stride-65,
// conflict-free), V (natural), bias^T (stride-65), Q rows. Computes
// scores = (q.k + q.bias)/sqrt(128), faithful masked-fill(1e-10), softmax,
// emb1 = attn@V, emb2 = attn@bias; writes attn probs straight to d_out.
#define TI 8
#define ATTN_SMEM ((256*65 + 64*256 + 128*65 + TI*256 + 128 + 16) * 4)

__global__ __launch_bounds__(256) void attn_kernel(
    const float* __restrict__ q, const float* __restrict__ k,
    const float* __restrict__ v, const float* __restrict__ bias,
    const void* __restrict__ mask, float* __restrict__ aout,
    float* __restrict__ att)
{
    extern __shared__ float sm[];
    float* kT  = sm;                   // [256][65]
    float* vs  = kT + 256*65;          // [64][256]
    float* bT  = vs + 64*256;          // [128][65]
    float* qs  = bT + 128*65;          // [TI][256]
    float* sa  = qs + TI*256;          // attn probs [2][64]
    float* red = sa + 128;             // [16]

    const int b   = blockIdx.x;
    const int it0 = blockIdx.y * TI;
    const int t   = threadIdx.x;
    const int mode = g_mask_mode;

    // K transposed into SMEM (global coalesced, STS conflict-free: 65 % 32 == 1)
    const float* kb = k + (size_t)b * 64 * 256;
    #pragma unroll 4
    for (int j = 0; j < 64; j++) kT[t * 65 + j] = kb[j * 256 + t];
    // V natural layout
    const float4* vb = (const float4*)(v + (size_t)b * 64 * 256);
    float4* vs4 = (float4*)vs;
    #pragma unroll
    for (int p = t; p < 4096; p += 256) vs4[p] = vb[p];
    // Q rows
    const float4* qb = (const float4*)(q + ((size_t)b * 64 + it0) * 256);
    float4* qs4 = (float4*)qs;
    #pragma unroll
    for (int p = t; p < TI * 64; p += 256) qs4[p] = qb[p];
    __syncthreads();

    const float invT = 0.0883883476483184405f; // 1/sqrt(128)

    for (int ii = 0; ii < TI; ii++) {
        const int i = it0 + ii;
        // bias row-block transposed: LDG coalesced, STS conflict-free.
        const float* bb = bias + ((size_t)(b * 64 + i)) * 64 * 128;
        #pragma unroll 8
        for (int p = t; p < 8192; p += 256) {
            int j = p >> 7, d = p & 127;
            bT[d * 65 + j] = bb[p];
        }
        __syncthreads();

        const int h = (t >> 6) & 1, j = t & 63;
        float s;
        if (t < 128) {
            const float* qrow = qs + ii * 256 + h * 128;
            const float* kcol = kT + (h * 128) * 65 + j;
            const float* bcol = bT + j;
            float a1 = 0.0f, a2 = 0.0f;
            #pragma unroll 4
            for (int d = 0; d < 128; d++) {
                float qd = qrow[d];
                a1 += qd * kcol[d * 65];
                a2 += qd * bcol[d * 65];
            }
            s = (a1 + a2) * invT;
            if (mask_at(mask, ((b * 64 + i) << 6) + j, mode)) s = 1e-10f;
        } else {
            s = -3.4e38f;
        }
        float m = s;
        #pragma unroll
        for (int o = 16; o; o >>= 1) m = fmaxf(m, __shfl_xor_sync(0xffffffffu, m, o));
        if ((t & 31) == 0) red[t >> 5] = m;
        __syncthreads();
        float e = 0.0f;
        if (t < 128) {
            float hm = fmaxf(red[h * 2], red[h * 2 + 1]);
            e = expf(s - hm);
        }
        float ws = e;
        #pragma unroll
        for (int o = 16; o; o >>= 1) ws += __shfl_xor_sync(0xffffffffu, ws, o);
        if ((t & 31) == 0) red[8 + (t >> 5)] = ws;
        __syncthreads();
        if (t < 128) {
            float hs = red[8 + h * 2] + red[8 + h * 2 + 1];
            float a = e / hs;
            sa[t] = a;
            aout[((size_t)(h * 64 + b)) * 4096 + i * 64 + j] = a;
        }
        __syncthreads();
        // emb1 + emb2 (all 256 threads: thread = (head, dim))
        {
            const int h2 = t >> 7, dd = t & 127;
            const float* vcol = vs + h2 * 128 + dd;
            const float* brow = bT + dd * 65;
            const float* arow = sa + h2 * 64;
            float e1 = 0.0f, e2 = 0.0f;
            #pragma unroll 4
            for (int jj = 0; jj < 64; jj++) {
                float a = arow[jj];
                e1 += a * vcol[jj * 256];
                e2 += a * brow[jj];
            }
            att[((size_t)(b * 64 + i)) * 256 + h2 * 128 + dd] = e1 + e2;
        }
        __syncthreads();
    }
}

// ------------------------- mean pool ---------------------------------------
__global__ __launch_bounds__(128) void mean_kernel(
    const float* __restrict__ emb, float* __restrict__ out)
{
    int b = blockIdx.x, d = threadIdx.x;
    float s = 0.0f;
    #pragma unroll 4
    for (int n = 0; n < 64; n++) s += emb[((size_t)b * 64 + n) * Dm + d];
    out[b * Dm + d] = s * (1.0f / 64.0f);
}

// ---------------------------------------------------------------------------
extern "C" void kernel_launch(void* const* d_in, const int* in_sizes, int n_in,
                              void* d_out, int out_size)
{
    // Resolve mask position: metadata is either setup_inputs dict order
    // (mask at idx 3) or reference-signature order (mask last). The mask's
    // element count (262144) is unique among all inputs.
    int mi = (in_sizes[3] == 262144) ? 3 : (n_in - 1);
    int wb = (mi == 3) ? 4 : 3;  // index of Wn

    const float* node = (const float*)d_in[0];
    const float* stpe = (const float*)d_in[1];
    const float* edge = (const float*)d_in[2];
    const void*  mask = d_in[mi];
    const float* Wn   = (const float*)d_in[wb + 0];
    const float* bn   = (const float*)d_in[wb + 1];
    const float* We   = (const float*)d_in[wb + 2];
    const float* be   = (const float*)d_in[wb + 3];
    const float* ln1g = (const float*)d_in[wb + 4];
    const float* ln1b = (const float*)d_in[wb + 5];
    const float* Wq   = (const float*)d_in[wb + 6];
    const float* Wk   = (const float*)d_in[wb + 7];
    const float* Wv   = (const float*)d_in[wb + 8];
    const float* Wo   = (const float*)d_in[wb + 9];
    const float* bo   = (const float*)d_in[wb + 10];
    const float* ln2g = (const float*)d_in[wb + 11];
    const float* ln2b = (const float*)d_in[wb + 12];
    const float* W1   = (const float*)d_in[wb + 13];
    const float* b1   = (const float*)d_in[wb + 14];
    const float* W2   = (const float*)d_in[wb + 15];
    const float* b2   = (const float*)d_in[wb + 16];
    float* out = (float*)d_out;

    cudaFuncSetAttribute(attn_kernel,
                         cudaFuncAttributeMaxDynamicSharedMemorySize, ATTN_SMEM);

    float *p_emb, *p_h, *p_q, *p_k, *p_v, *p_att, *p_mid, *p_bias;
    cudaGetSymbolAddress((void**)&p_emb,  g_emb);
    cudaGetSymbolAddress((void**)&p_h,    g_h);
    cudaGetSymbolAddress((void**)&p_q,    g_q);
    cudaGetSymbolAddress((void**)&p_k,    g_k);
    cudaGetSymbolAddress((void**)&p_v,    g_v);
    cudaGetSymbolAddress((void**)&p_att,  g_att);
    cudaGetSymbolAddress((void**)&p_mid,  g_mid);
    cudaGetSymbolAddress((void**)&p_bias, g_bias);

    detect_mask_kernel<<<1, 256>>>((const unsigned int*)mask);

    // emb = cat(node, stpe) @ Wn + bn
    gemm64<<<dim3(64, 2), 256>>>(node, Wn,            bn,      nullptr, p_emb,
                                 ROWS, 128, 128, 0);
    gemm64<<<dim3(64, 2), 256>>>(stpe, Wn + 128 * 128, nullptr, p_emb,   p_emb,
                                 ROWS, 128, 128, 0);

    for (int l = 0; l < Ll; l++) {
        // pre-attention LN
        ln_kernel<<<ROWS, 128>>>(p_emb, ln1g + l * 128, ln1b + l * 128, p_h, 1e-5f);
        // QKV projections (no bias)
        gemm64<<<dim3(64, 4), 256>>>(p_h, Wq + (size_t)l * 128 * 256, nullptr, nullptr,
                                     p_q, ROWS, 256, 128, 0);
        gemm64<<<dim3(64, 4), 256>>>(p_h, Wk + (size_t)l * 128 * 256, nullptr, nullptr,
                                     p_k, ROWS, 256, 128, 0);
        gemm64<<<dim3(64, 4), 256>>>(p_h, Wv + (size_t)l * 128 * 256, nullptr, nullptr,
                                     p_v, ROWS, 256, 128, 0);
        // edge bias = edge_feat @ We[l] + be[l]
        gemm128<<<EDGE_M / 128, 256>>>(edge, We + (size_t)l * 128 * 128,
                                       be + l * 128, p_bias);
        // fused attention; attn probs go straight into d_out
        attn_kernel<<<dim3(64, 64 / TI), 256, ATTN_SMEM>>>(
            p_q, p_k, p_v, p_bias, mask,
            out + 8192 + (size_t)l * 2 * 64 * 4096, p_att);
        // output projection + residual
        gemm64<<<dim3(64, 2), 256>>>(p_att, Wo + (size_t)l * 256 * 128,
                                     bo + l * 128, p_emb, p_emb, ROWS, 128, 256, 0);
        // FFN
        ln_kernel<<<ROWS, 128>>>(p_emb, ln2g + l * 128, ln2b + l * 128, p_h, 1e-6f);
        gemm64<<<dim3(64, 8), 256>>>(p_h, W1 + (size_t)l * 128 * 512,
                                     b1 + l * 512, nullptr, p_mid, ROWS, 512, 128, 1);
        gemm64<<<dim3(64, 2), 256>>>(p_mid, W2 + (size_t)l * 512 * 128,
                                     b2 + l * 128, p_emb, p_emb, ROWS, 128, 512, 0);
    }

    mean_kernel<<<64, 128>>>(p_emb, out);
}

// round 2
// speedup vs baseline: 1.7260x; 1.7260x over previous
#include <cuda_runtime.h>
#include <cuda_bf16.h>
#include <math.h>
#include <stdint.h>

// ---------------------------------------------------------------------------
// TGAN: 2-layer graph transformer with edge-bias attention.
// B=64, N=64, D=128, NH=2 (d_k=128), L=2.
// Key optimization: bias = edge@We + be is NEVER materialized.
//   attn2 = (q We^T) . edge + q.be          (qe GEMM + in-kernel dot)
//   emb2  = (attn @ edge) @ We + be         (ce accumulated in-kernel)
// ---------------------------------------------------------------------------

#define Bb 64
#define Nn 64
#define Dm 128
#define Ll 2
#define ROWS (Bb*Nn)          // 4096
#define TI 8

// ------------------------- scratch (device globals) ------------------------
__device__ float g_emb [ROWS*Dm];
__device__ float g_h   [ROWS*Dm];
__device__ float g_q   [ROWS*2*Dm];
__device__ float g_k   [ROWS*2*Dm];
__device__ float g_v   [ROWS*2*Dm];
__device__ float g_qe  [ROWS*2*Dm];        // q @ We^T per head
__device__ float g_ce  [ROWS*2*Dm];        // attn @ edge per head
__device__ float g_att [ROWS*2*Dm];        // MHA concat output
__device__ float g_mid [ROWS*4*Dm];        // FFN mid
__device__ float g_WeT [Dm*Dm];            // We transposed (per-layer, reused)
__device__ int   g_mask_mode;

// ------------------------- mask dtype autodetect ---------------------------
__global__ void detect_mask_kernel(const unsigned int* __restrict__ m) {
    __shared__ int s_flags;
    if (threadIdx.x == 0) s_flags = 0;
    __syncthreads();
    int f = 0;
    for (int p = threadIdx.x; p < 65536; p += blockDim.x) {
        unsigned w = m[p];
        if (w > 1u) f |= 1;
        if (w != 0u && w != 0x3F800000u) f |= 2;
    }
    if (f) atomicOr(&s_flags, f);
    __syncthreads();
    if (threadIdx.x == 0) {
        int fl = s_flags;
        g_mask_mode = (!(fl & 1)) ? 0 : ((!(fl & 2)) ? 1 : 2);
    }
}

__device__ __forceinline__ bool mask_at(const void* m, int idx, int mode) {
    if (mode == 0) return ((const int*)m)[idx] != 0;
    if (mode == 1) return ((const float*)m)[idx] != 0.0f;
    return ((const unsigned char*)m)[idx] != 0;
}

// ------------------------- LayerNorm (row = 128) ---------------------------
__global__ __launch_bounds__(128) void ln_kernel(
    const float* __restrict__ x, const float* __restrict__ g,
    const float* __restrict__ b, float* __restrict__ y, float eps)
{
    int row = blockIdx.x, t = threadIdx.x;
    float v = x[(size_t)row*Dm + t];
    float s = v;
    #pragma unroll
    for (int o = 16; o; o >>= 1) s += __shfl_xor_sync(0xffffffffu, s, o);
    __shared__ float red[8];
    if ((t & 31) == 0) red[t >> 5] = s;
    __syncthreads();
    float mean = (red[0] + red[1] + red[2] + red[3]) * (1.0f / 128.0f);
    float d = v - mean;
    float q = d * d;
    #pragma unroll
    for (int o = 16; o; o >>= 1) q += __shfl_xor_sync(0xffffffffu, q, o);
    if ((t & 31) == 0) red[4 + (t >> 5)] = q;
    __syncthreads();
    float var = (red[4] + red[5] + red[6] + red[7]) * (1.0f / 128.0f);
    y[(size_t)row*Dm + t] = d * rsqrtf(var + eps) * g[t] + b[t];
}

// ------------------------- 128x128 transpose -------------------------------
__global__ __launch_bounds__(256) void transpose128_kernel(
    const float* __restrict__ in, float* __restrict__ out)
{
    int idx = blockIdx.x * 256 + threadIdx.x;  // 0..16383
    int kk = idx >> 7, e = idx & 127;
    out[idx] = __ldg(&in[e * 128 + kk]);       // out[k,e] = in[e,k]
}

// ------------------------- generic small SGEMM -----------------------------
// C[M,N] = A[M,K](stride sA) @ W[K,N] (+bias) (+res stride sR) (relu),
// C stride sC. BM=BN=64, 256 thr, 4x4 micro-tile.
__global__ __launch_bounds__(256) void gemm64(
    const float* __restrict__ A, int sA, const float* __restrict__ W,
    const float* __restrict__ bias, const float* res, int sR,
    float* C, int sC, int M, int N, int K, int relu)
{
    __shared__ __align__(16) float AsT[16][68];
    __shared__ __align__(16) float Ws [16][64];
    const int m0 = blockIdx.x * 64, n0 = blockIdx.y * 64;
    const int t = threadIdx.x;
    const int lm = t >> 2, lk = (t & 3) * 4;
    const int wk = t >> 4, wn = (t & 15) * 4;
    const int tmi = t >> 4, tni = t & 15;

    float acc[4][4];
    #pragma unroll
    for (int i = 0; i < 4; i++)
        #pragma unroll
        for (int j = 0; j < 4; j++) acc[i][j] = 0.0f;

    for (int k0 = 0; k0 < K; k0 += 16) {
        float4 a = *(const float4*)&A[(size_t)(m0 + lm) * sA + k0 + lk];
        float4 w = *(const float4*)&W[(size_t)(k0 + wk) * N + n0 + wn];
        __syncthreads();
        AsT[lk+0][lm] = a.x; AsT[lk+1][lm] = a.y;
        AsT[lk+2][lm] = a.z; AsT[lk+3][lm] = a.w;
        *(float4*)&Ws[wk][wn] = w;
        __syncthreads();
        #pragma unroll
        for (int kk = 0; kk < 16; kk++) {
            float4 av = *(const float4*)&AsT[kk][tmi * 4];
            float4 wv = *(const float4*)&Ws [kk][tni * 4];
            float aa[4] = {av.x, av.y, av.z, av.w};
            float ww[4] = {wv.x, wv.y, wv.z, wv.w};
            #pragma unroll
            for (int i = 0; i < 4; i++)
                #pragma unroll
                for (int j = 0; j < 4; j++) acc[i][j] += aa[i] * ww[j];
        }
    }

    float bv[4] = {0, 0, 0, 0};
    if (bias) {
        float4 b4 = *(const float4*)&bias[n0 + tni * 4];
        bv[0] = b4.x; bv[1] = b4.y; bv[2] = b4.z; bv[3] = b4.w;
    }
    #pragma unroll
    for (int i = 0; i < 4; i++) {
        size_t row = (size_t)(m0 + tmi * 4 + i);
        float o[4];
        #pragma unroll
        for (int j = 0; j < 4; j++) o[j] = acc[i][j] + bv[j];
        if (res) {
            float4 r = *(const float4*)&res[row * sR + n0 + tni * 4];
            o[0] += r.x; o[1] += r.y; o[2] += r.z; o[3] += r.w;
        }
        if (relu) {
            #pragma unroll
            for (int j = 0; j < 4; j++) o[j] = fmaxf(o[j], 0.0f);
        }
        float4 st; st.x = o[0]; st.y = o[1]; st.z = o[2]; st.w = o[3];
        *(float4*)&C[row * sC + n0 + tni * 4] = st;
    }
}

// ------------------------- fused attention v2 ------------------------------
// Block = (batch b, tile of TI query rows). SMEM: K^T [256][65], V [64][256],
// q/qe rows, edge^T [128][65] per i. Computes scores = (q.k + qe.edge + q.be)
// / sqrt(128), faithful masked-fill(1e-10), softmax, emb1 = attn@V (+be for
// emb2's additive term), ce = attn@edge. attn probs go straight to d_out.
#define ATTN_SMEM ((256*65 + 64*256 + TI*256*2 + 128*65 + 256 + 128 + 128 + 16 + 16) * 4)

__global__ __launch_bounds__(256) void attn2_kernel(
    const float* __restrict__ q, const float* __restrict__ k,
    const float* __restrict__ v, const float* __restrict__ qe,
    const float* __restrict__ edge, const float* __restrict__ be,
    const void* __restrict__ mask, float* __restrict__ aout,
    float* __restrict__ att, float* __restrict__ ce)
{
    extern __shared__ float sm[];
    float* kT  = sm;                   // [256][65]  kT[d*65+j] = k[b,j,d]
    float* vs  = kT + 256*65;          // [64][256]  natural
    float* qs  = vs + 64*256;          // [TI][256]
    float* qes = qs + TI*256;          // [TI][256]
    float* eT  = qes + TI*256;         // [128][65]  eT[e*65+j] = edge[b,i,j,e]
    float* part= eT + 128*65;          // [256] score partials
    float* sa  = part + 256;           // [128] attn probs (2 heads x 64)
    float* bes = sa + 128;             // [128]
    float* red = bes + 128;            // [16]
    float* qbe = red + 16;             // [16]  q.be per (h, ii)

    const int b   = blockIdx.x;
    const int it0 = blockIdx.y * TI;
    const int t   = threadIdx.x;
    const int mode = g_mask_mode;

    // K transposed (coalesced LDG, conflict-free STS: stride 65)
    const float* kb = k + (size_t)b * 64 * 256;
    #pragma unroll 8
    for (int j = 0; j < 64; j++) kT[t * 65 + j] = kb[j * 256 + t];
    // V natural
    {
        const float4* vb = (const float4*)(v + (size_t)b * 64 * 256);
        float4* vs4 = (float4*)vs;
        #pragma unroll
        for (int p = t; p < 4096; p += 256) vs4[p] = vb[p];
    }
    // Q and QE rows for this tile
    {
        const float4* qb  = (const float4*)(q  + ((size_t)b * 64 + it0) * 256);
        const float4* qeb = (const float4*)(qe + ((size_t)b * 64 + it0) * 256);
        float4* qs4  = (float4*)qs;
        float4* qes4 = (float4*)qes;
        #pragma unroll
        for (int p = t; p < TI * 64; p += 256) { qs4[p] = qb[p]; qes4[p] = qeb[p]; }
    }
    if (t < 128) bes[t] = be[t];
    __syncthreads();

    // qbe[h][ii] = dot(q_row(h), be): 16 tasks over 8 warps
    {
        int w = t >> 5, lane = t & 31;
        #pragma unroll
        for (int r = 0; r < 2; r++) {
            int task = w * 2 + r;
            int h = task >> 3, ii = task & 7;
            const float* qrow = qs + ii * 256 + h * 128;
            float s = qrow[lane] * bes[lane] + qrow[64 + lane] * bes[64 + lane];
            #pragma unroll
            for (int o = 16; o; o >>= 1) s += __shfl_xor_sync(0xffffffffu, s, o);
            if (lane == 0) qbe[task] = s;
        }
    }

    const float invT = 0.0883883476483184405f; // 1/sqrt(128)

    for (int ii = 0; ii < TI; ii++) {
        const int i = it0 + ii;
        __syncthreads();   // protect eT/sa reuse from previous iteration
        // edge row-block -> eT (coalesced LDG.128)
        {
            const float4* eb4 = (const float4*)(edge + ((size_t)(b * 64 + i)) * 8192);
            #pragma unroll
            for (int p = t; p < 2048; p += 256) {
                float4 val = eb4[p];
                int j = p >> 5, e = (p & 31) * 4;
                eT[(e+0) * 65 + j] = val.x;
                eT[(e+1) * 65 + j] = val.y;
                eT[(e+2) * 65 + j] = val.z;
                eT[(e+3) * 65 + j] = val.w;
            }
        }
        __syncthreads();

        // score partials: all 256 threads, (h,j) x half-of-d
        {
            int hj = t & 127, half = t >> 7;
            int h = hj >> 6, j = hj & 63;
            const float* qrow = qs  + ii * 256 + h * 128 + half * 64;
            const float* qer  = qes + ii * 256 + h * 128 + half * 64;
            const float* kcol = kT + (h * 128 + half * 64) * 65 + j;
            const float* ecol = eT + (half * 64) * 65 + j;
            float a = 0.0f;
            #pragma unroll 8
            for (int d = 0; d < 64; d++) {
                a += qrow[d] * kcol[d * 65];
                a += qer[d]  * ecol[d * 65];
            }
            part[t] = a;
        }
        __syncthreads();

        int h = (t >> 6) & 1, j = t & 63;
        float s = -3.4e38f, ex = 0.0f;
        if (t < 128) {
            s = (part[t] + part[t + 128] + qbe[h * 8 + ii]) * invT;
            if (mask_at(mask, ((b * 64 + i) << 6) + j, mode)) s = 1e-10f;
            float m = s;
            #pragma unroll
            for (int o = 16; o; o >>= 1)
                m = fmaxf(m, __shfl_xor_sync(0xffffffffu, m, o));
            if ((t & 31) == 0) red[t >> 5] = m;
        }
        __syncthreads();
        if (t < 128) {
            float hm = fmaxf(red[h * 2], red[h * 2 + 1]);
            ex = expf(s - hm);
            float ws = ex;
            #pragma unroll
            for (int o = 16; o; o >>= 1) ws += __shfl_xor_sync(0xffffffffu, ws, o);
            if ((t & 31) == 0) red[8 + (t >> 5)] = ws;
        }
        __syncthreads();
        if (t < 128) {
            float a = ex / (red[8 + h * 2] + red[8 + h * 2 + 1]);
            sa[t] = a;
            aout[((size_t)(h * 64 + b)) * 4096 + i * 64 + j] = a;
        }
        __syncthreads();

        // emb1 = attn@V, ce = attn@edge; be is emb2's additive term
        {
            int h2 = t >> 7, dd = t & 127;
            const float* arow = sa + h2 * 64;
            const float* vcol = vs + h2 * 128 + dd;
            const float* erow = eT + dd * 65;
            float e1 = 0.0f, ec = 0.0f;
            #pragma unroll 8
            for (int jj = 0; jj < 64; jj++) {
                float a = arow[jj];
                e1 += a * vcol[jj * 256];
                ec += a * erow[jj];
            }
            size_t row = (size_t)(b * 64 + i);
            att[row * 256 + h2 * 128 + dd] = e1 + bes[dd];
            ce [row * 256 + h2 * 128 + dd] = ec;
        }
    }
}

// ------------------------- mean pool ---------------------------------------
__global__ __launch_bounds__(128) void mean_kernel(
    const float* __restrict__ emb, float* __restrict__ out)
{
    int b = blockIdx.x, d = threadIdx.x;
    float s = 0.0f;
    #pragma unroll 4
    for (int n = 0; n < 64; n++) s += emb[((size_t)b * 64 + n) * Dm + d];
    out[b * Dm + d] = s * (1.0f / 64.0f);
}

// ---------------------------------------------------------------------------
extern "C" void kernel_launch(void* const* d_in, const int* in_sizes, int n_in,
                              void* d_out, int out_size)
{
    int mi = (in_sizes[3] == 262144) ? 3 : (n_in - 1);
    int wb = (mi == 3) ? 4 : 3;

    const float* node = (const float*)d_in[0];
    const float* stpe = (const float*)d_in[1];
    const float* edge = (const float*)d_in[2];
    const void*  mask = d_in[mi];
    const float* Wn   = (const float*)d_in[wb + 0];
    const float* bn   = (const float*)d_in[wb + 1];
    const float* We   = (const float*)d_in[wb + 2];
    const float* be   = (const float*)d_in[wb + 3];
    const float* ln1g = (const float*)d_in[wb + 4];
    const float* ln1b = (const float*)d_in[wb + 5];
    const float* Wq   = (const float*)d_in[wb + 6];
    const float* Wk   = (const float*)d_in[wb + 7];
    const float* Wv   = (const float*)d_in[wb + 8];
    const float* Wo   = (const float*)d_in[wb + 9];
    const float* bo   = (const float*)d_in[wb + 10];
    const float* ln2g = (const float*)d_in[wb + 11];
    const float* ln2b = (const float*)d_in[wb + 12];
    const float* W1   = (const float*)d_in[wb + 13];
    const float* b1   = (const float*)d_in[wb + 14];
    const float* W2   = (const float*)d_in[wb + 15];
    const float* b2   = (const float*)d_in[wb + 16];
    float* out = (float*)d_out;

    cudaFuncSetAttribute(attn2_kernel,
                         cudaFuncAttributeMaxDynamicSharedMemorySize, ATTN_SMEM);

    float *p_emb, *p_h, *p_q, *p_k, *p_v, *p_qe, *p_ce, *p_att, *p_mid, *p_WeT;
    cudaGetSymbolAddress((void**)&p_emb, g_emb);
    cudaGetSymbolAddress((void**)&p_h,   g_h);
    cudaGetSymbolAddress((void**)&p_q,   g_q);
    cudaGetSymbolAddress((void**)&p_k,   g_k);
    cudaGetSymbolAddress((void**)&p_v,   g_v);
    cudaGetSymbolAddress((void**)&p_qe,  g_qe);
    cudaGetSymbolAddress((void**)&p_ce,  g_ce);
    cudaGetSymbolAddress((void**)&p_att, g_att);
    cudaGetSymbolAddress((void**)&p_mid, g_mid);
    cudaGetSymbolAddress((void**)&p_WeT, g_WeT);

    detect_mask_kernel<<<1, 256>>>((const unsigned int*)mask);

    // emb = cat(node, stpe) @ Wn + bn
    gemm64<<<dim3(64, 2), 256>>>(node, 128, Wn,             bn,      nullptr, 0,
                                 p_emb, 128, ROWS, 128, 128, 0);
    gemm64<<<dim3(64, 2), 256>>>(stpe, 128, Wn + 128 * 128, nullptr, p_emb, 128,
                                 p_emb, 128, ROWS, 128, 128, 0);

    for (int l = 0; l < Ll; l++) {
        const float* We_l = We + (size_t)l * 128 * 128;
        const float* be_l = be + l * 128;

        ln_kernel<<<ROWS, 128>>>(p_emb, ln1g + l * 128, ln1b + l * 128, p_h, 1e-5f);

        gemm64<<<dim3(64, 4), 256>>>(p_h, 128, Wq + (size_t)l * 128 * 256,
                                     nullptr, nullptr, 0, p_q, 256, ROWS, 256, 128, 0);
        gemm64<<<dim3(64, 4), 256>>>(p_h, 128, Wk + (size_t)l * 128 * 256,
                                     nullptr, nullptr, 0, p_k, 256, ROWS, 256, 128, 0);
        gemm64<<<dim3(64, 4), 256>>>(p_h, 128, Wv + (size_t)l * 128 * 256,
                                     nullptr, nullptr, 0, p_v, 256, ROWS, 256, 128, 0);

        // qe = q @ We^T (per head)
        transpose128_kernel<<<64, 256>>>(We_l, p_WeT);
        for (int h = 0; h < 2; h++)
            gemm64<<<dim3(64, 2), 256>>>(p_q + h * 128, 256, p_WeT,
                                         nullptr, nullptr, 0,
                                         p_qe + h * 128, 256, ROWS, 128, 128, 0);

        attn2_kernel<<<dim3(64, 64 / TI), 256, ATTN_SMEM>>>(
            p_q, p_k, p_v, p_qe, edge, be_l, mask,
            out + 8192 + (size_t)l * 2 * 64 * 4096, p_att, p_ce);

        // emb2 += ce @ We (per head; be term already added in attn kernel)
        for (int h = 0; h < 2; h++)
            gemm64<<<dim3(64, 2), 256>>>(p_ce + h * 128, 256, We_l,
                                         nullptr, p_att + h * 128, 256,
                                         p_att + h * 128, 256, ROWS, 128, 128, 0);

        // output projection + residual
        gemm64<<<dim3(64, 2), 256>>>(p_att, 256, Wo + (size_t)l * 256 * 128,
                                     bo + l * 128, p_emb, 128,
                                     p_emb, 128, ROWS, 128, 256, 0);

        // FFN
        ln_kernel<<<ROWS, 128>>>(p_emb, ln2g + l * 128, ln2b + l * 128, p_h, 1e-6f);
        gemm64<<<dim3(64, 8), 256>>>(p_h, 128, W1 + (size_t)l * 128 * 512,
                                     b1 + l * 512, nullptr, 0,
                                     p_mid, 512, ROWS, 512, 128, 1);
        gemm64<<<dim3(64, 2), 256>>>(p_mid, 512, W2 + (size_t)l * 512 * 128,
                                     b2 + l * 128, p_emb, 128,
                                     p_emb, 128, ROWS, 128, 512, 0);
    }

    mean_kernel<<<64, 128>>>(p_emb, out);
}

// round 4
// speedup vs baseline: 1.7692x; 1.0250x over previous
#include <cuda_runtime.h>
#include <cuda_bf16.h>
#include <math.h>
#include <stdint.h>

// ---------------------------------------------------------------------------
// TGAN: 2-layer graph transformer with edge-bias attention.
// B=64, N=64, D=128, NH=2 (d_k=128), L=2.
//   bias tensor never materialized:
//     attn2 = (h @ (Wq_h We^T)) . edge + q.be     (fused into QKVE GEMM)
//     emb2  = (attn @ edge) @ We + be             (fused into output GEMM)
//   All GEMMs use Blackwell fma.rn.f32x2 (2 fp32 FMA / instr).
// ---------------------------------------------------------------------------

#define Bb 64
#define Nn 64
#define Dm 128
#define Ll 2
#define ROWS (Bb*Nn)          // 4096
#define TI 16

typedef unsigned long long ull;

// ------------------------- scratch (device globals) ------------------------
__device__ float g_emb  [ROWS*Dm];
__device__ float g_qkv  [ROWS*1024];        // [q(256) | k(256) | v(256) | qe(256)]
__device__ float g_att  [ROWS*512];         // [emb1cat(256) | cecat(256)]
__device__ float g_mid  [ROWS*4*Dm];
__device__ float g_stats[ROWS*2];           // (mu, rsig) per row
__device__ float g_Wqe  [Ll*128*256];       // per layer: Wqe[k][h*128+e]
__device__ float g_Wce  [Ll*256*128];       // per layer: rows h*128+e
__device__ float g_cvec [Ll*128];
__device__ int   g_mask_mode;

// ------------------------- f32x2 helpers -----------------------------------
__device__ __forceinline__ ull ffma2(ull a, ull b, ull c) {
    ull d;
    asm("fma.rn.f32x2 %0, %1, %2, %3;" : "=l"(d) : "l"(a), "l"(b), "l"(c));
    return d;
}
__device__ __forceinline__ ull pack2(float x) {
    ull d;
    asm("mov.b64 %0, {%1, %2};" : "=l"(d)
        : "r"(__float_as_uint(x)), "r"(__float_as_uint(x)));
    return d;
}
__device__ __forceinline__ void unpack2(ull v, float& lo, float& hi) {
    unsigned a, b;
    asm("mov.b64 {%0, %1}, %2;" : "=r"(a), "=r"(b) : "l"(v));
    lo = __uint_as_float(a); hi = __uint_as_float(b);
}

// ------------------------- mask dtype autodetect ---------------------------
__global__ void detect_mask_kernel(const unsigned int* __restrict__ m) {
    __shared__ int s_flags;
    if (threadIdx.x == 0) s_flags = 0;
    __syncthreads();
    int f = 0;
    for (int p = threadIdx.x; p < 65536; p += blockDim.x) {
        unsigned w = m[p];
        if (w > 1u) f |= 1;
        if (w != 0u && w != 0x3F800000u) f |= 2;
    }
    if (f) atomicOr(&s_flags, f);
    __syncthreads();
    if (threadIdx.x == 0) {
        int fl = s_flags;
        g_mask_mode = (!(fl & 1)) ? 0 : ((!(fl & 2)) ? 1 : 2);
    }
}

__device__ __forceinline__ bool mask_at(const void* m, int idx, int mode) {
    if (mode == 0) return ((const int*)m)[idx] != 0;
    if (mode == 1) return ((const float*)m)[idx] != 0.0f;
    return ((const unsigned char*)m)[idx] != 0;
}

// ------------------------- LN row stats ------------------------------------
__global__ __launch_bounds__(256) void ln_stats_kernel(
    const float* __restrict__ x, float* __restrict__ st, float eps)
{
    int row = blockIdx.x * 8 + (threadIdx.x >> 5);
    int lane = threadIdx.x & 31;
    float4 v = ((const float4*)(x + (size_t)row * 128))[lane];
    float s = v.x + v.y + v.z + v.w;
    float q = v.x*v.x + v.y*v.y + v.z*v.z + v.w*v.w;
    #pragma unroll
    for (int o = 16; o; o >>= 1) {
        s += __shfl_xor_sync(0xffffffffu, s, o);
        q += __shfl_xor_sync(0xffffffffu, q, o);
    }
    if (lane == 0) {
        float mu = s * (1.0f / 128.0f);
        float var = q * (1.0f / 128.0f) - mu * mu;
        st[row*2] = mu;
        st[row*2+1] = rsqrtf(var + eps);
    }
}

// ------------------------- weight prep -------------------------------------
// Wqe[l][k][h*128+e] = sum_d Wq[l][k][h*128+d] * We[l][e][d]
__global__ __launch_bounds__(256) void prep_wqe_kernel(
    const float* __restrict__ Wq, const float* __restrict__ We)
{
    int l = blockIdx.y, k = blockIdx.x, he = threadIdx.x;
    int h = he >> 7, e = he & 127;
    const float* wq = Wq + (size_t)l*128*256 + k*256 + h*128;
    const float* we = We + (size_t)l*128*128 + e*128;
    float s = 0.0f;
    #pragma unroll 8
    for (int d = 0; d < 128; d++) s += wq[d] * we[d];
    g_Wqe[((size_t)l*128 + k)*256 + he] = s;
}

// Wce[l][h*128+e][n] = sum_d We[l][e][d] * Wo[l][h*128+d][n]
__global__ __launch_bounds__(128) void prep_wce_kernel(
    const float* __restrict__ We, const float* __restrict__ Wo)
{
    int l = blockIdx.y, he = blockIdx.x, n = threadIdx.x;
    int h = he >> 7, e = he & 127;
    const float* we = We + (size_t)l*128*128 + e*128;
    const float* wo = Wo + (size_t)l*256*128 + h*128*128;
    float s = 0.0f;
    #pragma unroll 8
    for (int d = 0; d < 128; d++) s += we[d] * wo[d*128 + n];
    g_Wce[((size_t)l*256 + he)*128 + n] = s;
}

// cvec[l][n] = bo[n] + sum_d be[d]*(Wo[d][n] + Wo[128+d][n])
__global__ __launch_bounds__(128) void prep_cvec_kernel(
    const float* __restrict__ be, const float* __restrict__ Wo,
    const float* __restrict__ bo)
{
    int l = blockIdx.x, n = threadIdx.x;
    const float* wo = Wo + (size_t)l*256*128;
    const float* bel = be + l*128;
    float s = bo[l*128 + n];
    #pragma unroll 8
    for (int d = 0; d < 128; d++)
        s += bel[d] * (wo[d*128 + n] + wo[(128+d)*128 + n]);
    g_cvec[l*128 + n] = s;
}

// ------------------------- universal GEMM (f32x2) --------------------------
// C[M,64*gy] = LN?(A)[M,K] @ W[K,...] (+bias)(+res)(relu)
// A: two-pointer split at aksplit (columns). W: 4-pointer n-select (wspan)
// plus 2nd pointer Wk2 for k-rows >= wksplit. BM=BN=64, 256 thr, 4x4.
__global__ __launch_bounds__(256) void gemmF(
    const float* __restrict__ A1, const float* __restrict__ A2, int aksplit, int sA,
    const float* __restrict__ lnst, const float* __restrict__ lng,
    const float* __restrict__ lnb,
    const float* __restrict__ Wp0, const float* __restrict__ Wp1,
    const float* __restrict__ Wp2, const float* __restrict__ Wp3,
    int wspan, int sW,
    const float* __restrict__ Wk2, int wksplit, int sW2,
    const float* __restrict__ bias, const float* __restrict__ res, int sR,
    float* __restrict__ C, int sC, int K, int relu)
{
    __shared__ __align__(16) float AsT[16][68];
    __shared__ __align__(16) float Ws [16][64];
    const int m0 = blockIdx.x * 64, n0 = blockIdx.y * 64;
    const int t = threadIdx.x;
    const int lm = t >> 2, lk = (t & 3) * 4;
    const int wk = t >> 4, wn = (t & 15) * 4;
    const int tmi = t >> 4, tni = t & 15;

    const float* Wsel; int noff;
    {
        int sel = n0 / wspan; noff = n0 - sel * wspan;
        Wsel = (sel == 0) ? Wp0 : (sel == 1) ? Wp1 : (sel == 2) ? Wp2 : Wp3;
    }

    float2 st = make_float2(0.0f, 1.0f);
    if (lnst) st = *(const float2*)(lnst + (size_t)(m0 + lm) * 2);

    ull acc[4][2];
    ull z = pack2(0.0f);
    #pragma unroll
    for (int i = 0; i < 4; i++) { acc[i][0] = z; acc[i][1] = z; }

    // --- loaders ---
    auto loadA = [&](int k0) -> float4 {
        int kc = k0 + lk;
        const float* Ap = (kc < aksplit)
            ? A1 + (size_t)(m0 + lm) * sA + kc
            : A2 + (size_t)(m0 + lm) * sA + (kc - aksplit);
        float4 v = *(const float4*)Ap;
        if (lnst) {
            float4 g4 = *(const float4*)(lng + kc);
            float4 b4 = *(const float4*)(lnb + kc);
            v.x = (v.x - st.x) * st.y * g4.x + b4.x;
            v.y = (v.y - st.x) * st.y * g4.y + b4.y;
            v.z = (v.z - st.x) * st.y * g4.z + b4.z;
            v.w = (v.w - st.x) * st.y * g4.w + b4.w;
        }
        return v;
    };
    auto loadW = [&](int k0) -> float4 {
        int r = k0 + wk;
        const float* row = (r < wksplit)
            ? Wsel + (size_t)r * sW + noff
            : Wk2 + (size_t)(r - wksplit) * sW2 + noff;
        return *(const float4*)(row + wn);
    };

    float4 a = loadA(0), w = loadW(0);
    for (int k0 = 0; k0 < K; k0 += 16) {
        __syncthreads();
        AsT[lk+0][lm] = a.x; AsT[lk+1][lm] = a.y;
        AsT[lk+2][lm] = a.z; AsT[lk+3][lm] = a.w;
        *(float4*)&Ws[wk][wn] = w;
        __syncthreads();
        if (k0 + 16 < K) { a = loadA(k0 + 16); w = loadW(k0 + 16); }
        #pragma unroll
        for (int kk = 0; kk < 16; kk++) {
            float4 av = *(const float4*)&AsT[kk][tmi * 4];
            ulonglong2 wv = *(const ulonglong2*)&Ws[kk][tni * 4];
            ull a0 = pack2(av.x), a1 = pack2(av.y);
            ull a2 = pack2(av.z), a3 = pack2(av.w);
            acc[0][0] = ffma2(a0, wv.x, acc[0][0]);
            acc[0][1] = ffma2(a0, wv.y, acc[0][1]);
            acc[1][0] = ffma2(a1, wv.x, acc[1][0]);
            acc[1][1] = ffma2(a1, wv.y, acc[1][1]);
            acc[2][0] = ffma2(a2, wv.x, acc[2][0]);
            acc[2][1] = ffma2(a2, wv.y, acc[2][1]);
            acc[3][0] = ffma2(a3, wv.x, acc[3][0]);
            acc[3][1] = ffma2(a3, wv.y, acc[3][1]);
        }
    }

    float bv[4] = {0, 0, 0, 0};
    if (bias) {
        float4 b4 = *(const float4*)&bias[n0 + tni * 4];
        bv[0] = b4.x; bv[1] = b4.y; bv[2] = b4.z; bv[3] = b4.w;
    }
    #pragma unroll
    for (int i = 0; i < 4; i++) {
        size_t row = (size_t)(m0 + tmi * 4 + i);
        float o[4];
        unpack2(acc[i][0], o[0], o[1]);
        unpack2(acc[i][1], o[2], o[3]);
        #pragma unroll
        for (int j = 0; j < 4; j++) o[j] += bv[j];
        if (res) {
            float4 r = *(const float4*)&res[row * sR + n0 + tni * 4];
            o[0] += r.x; o[1] += r.y; o[2] += r.z; o[3] += r.w;
        }
        if (relu) {
            #pragma unroll
            for (int j = 0; j < 4; j++) o[j] = fmaxf(o[j], 0.0f);
        }
        float4 stv; stv.x = o[0]; stv.y = o[1]; stv.z = o[2]; stv.w = o[3];
        *(float4*)&C[row * sC + n0 + tni * 4] = stv;
    }
}

// ------------------------- fused attention v3 ------------------------------
// No edge transpose in SMEM: score phase = warp-per-j with coalesced global
// row reads of edge and k (L1-resident); ce phase re-reads edge column-wise
// (coalesced, L1-hot). smem ~100KB -> 2 blocks/SM; TI=16 -> 256 blocks.
#define ATTN_SMEM ((16384 + TI*256*2 + 128 + 128 + 128 + 16 + 32) * 4)

__global__ __launch_bounds__(256) void attn3_kernel(
    const float* __restrict__ qkv, const float* __restrict__ edge,
    const float* __restrict__ be, const void* __restrict__ mask,
    float* __restrict__ aout, float* __restrict__ att)
{
    extern __shared__ float sm[];
    float* vs   = sm;              // [64][256]
    float* qs   = vs + 16384;      // [TI][256]
    float* qes  = qs + TI*256;     // [TI][256]
    float* sraw = qes + TI*256;    // [128]
    float* sa   = sraw + 128;      // [128]
    float* bes  = sa + 128;        // [128]
    float* red  = bes + 128;       // [16]
    float* qbe  = red + 16;        // [32]

    const int b = blockIdx.x, it0 = blockIdx.y * TI, t = threadIdx.x;
    const int w = t >> 5, lane = t & 31;
    const int mode = g_mask_mode;
    const float4* qkv4 = (const float4*)qkv;
    const float4* edge4 = (const float4*)edge;

    // V rows (cols 512..767 of qkv)
    #pragma unroll
    for (int p = t; p < 4096; p += 256) {
        int j = p >> 6, c = p & 63;
        ((float4*)vs)[p] = qkv4[(size_t)(b * 64 + j) * 256 + 128 + c];
    }
    // Q (cols 0..255) and QE (cols 768..1023) for this tile
    #pragma unroll
    for (int p = t; p < TI * 64; p += 256) {
        int r = p >> 6, c = p & 63;
        ((float4*)qs)[p]  = qkv4[(size_t)(b * 64 + it0 + r) * 256 + c];
        ((float4*)qes)[p] = qkv4[(size_t)(b * 64 + it0 + r) * 256 + 192 + c];
    }
    if (t < 128) bes[t] = be[t];
    __syncthreads();

    // qbe[h*16+ii] = q_h(row ii) . be    (32 tasks over 8 warps)
    #pragma unroll
    for (int r = 0; r < 4; r++) {
        int task = w * 4 + r;
        int h = task >> 4, ii = task & 15;
        const float* qrow = qs + ii * 256 + h * 128;
        float s = 0.0f;
        #pragma unroll
        for (int c = 0; c < 4; c++) s += qrow[lane + 32*c] * bes[lane + 32*c];
        #pragma unroll
        for (int o = 16; o; o >>= 1) s += __shfl_xor_sync(0xffffffffu, s, o);
        if (lane == 0) qbe[task] = s;
    }

    const float invT = 0.0883883476483184405f;  // 1/sqrt(128)
    const float4* qs4 = (const float4*)qs;
    const float4* qes4 = (const float4*)qes;

    for (int ii = 0; ii < TI; ii++) {
        const int i = it0 + ii;
        __syncthreads();

        // ---- scores: warp w handles j = w*8 .. w*8+7 ----
        {
            float4 q1 = qs4[ii*64 + lane],      q2 = qs4[ii*64 + 32 + lane];
            float4 g1 = qes4[ii*64 + lane],     g2 = qes4[ii*64 + 32 + lane];
            size_t erow0 = (size_t)(b * 64 + i) * 64;
            float s1[8], s2[8];
            #pragma unroll
            for (int r = 0; r < 8; r++) {
                int j = w * 8 + r;
                float4 ee = edge4[(erow0 + j) * 32 + lane];
                float4 ka = qkv4[(size_t)(b * 64 + j) * 256 + 64 + lane];
                float4 kb = qkv4[(size_t)(b * 64 + j) * 256 + 96 + lane];
                s1[r] = q1.x*ka.x + q1.y*ka.y + q1.z*ka.z + q1.w*ka.w
                      + g1.x*ee.x + g1.y*ee.y + g1.z*ee.z + g1.w*ee.w;
                s2[r] = q2.x*kb.x + q2.y*kb.y + q2.z*kb.z + q2.w*kb.w
                      + g2.x*ee.x + g2.y*ee.y + g2.z*ee.z + g2.w*ee.w;
            }
            #pragma unroll
            for (int o = 16; o; o >>= 1) {
                #pragma unroll
                for (int r = 0; r < 8; r++) {
                    s1[r] += __shfl_xor_sync(0xffffffffu, s1[r], o);
                    s2[r] += __shfl_xor_sync(0xffffffffu, s2[r], o);
                }
            }
            if (lane == 0) {
                #pragma unroll
                for (int r = 0; r < 8; r++) {
                    sraw[w * 8 + r]      = s1[r];
                    sraw[64 + w * 8 + r] = s2[r];
                }
            }
        }
        __syncthreads();

        // ---- softmax (threads 0..127 = (h, j)) ----
        int h = (t >> 6) & 1, j = t & 63;
        float s = -3.4e38f, ex = 0.0f;
        if (t < 128) {
            s = (sraw[t] + qbe[h * 16 + ii]) * invT;
            if (mask_at(mask, ((b * 64 + i) << 6) + j, mode)) s = 1e-10f;
            float m = s;
            #pragma unroll
            for (int o = 16; o; o >>= 1)
                m = fmaxf(m, __shfl_xor_sync(0xffffffffu, m, o));
            if ((t & 31) == 0) red[t >> 5] = m;
        }
        __syncthreads();
        if (t < 128) {
            float hm = fmaxf(red[h * 2], red[h * 2 + 1]);
            ex = expf(s - hm);
            float ws = ex;
            #pragma unroll
            for (int o = 16; o; o >>= 1) ws += __shfl_xor_sync(0xffffffffu, ws, o);
            if ((t & 31) == 0) red[8 + (t >> 5)] = ws;
        }
        __syncthreads();
        if (t < 128) {
            float a = ex / (red[8 + h * 2] + red[8 + h * 2 + 1]);
            sa[t] = a;
            aout[((size_t)(h * 64 + b)) * 4096 + i * 64 + j] = a;
        }
        __syncthreads();

        // ---- emb1 = attn@V (smem), ce = attn@edge (global, L1-hot) ----
        {
            int h2 = t >> 7, dd = t & 127;
            const float* arow = sa + h2 * 64;
            const float* vcol = vs + h2 * 128 + dd;
            const float* ecol = edge + (size_t)(b * 64 + i) * 8192 + dd;
            float e1 = 0.0f, ec = 0.0f;
            #pragma unroll 8
            for (int jj = 0; jj < 64; jj++) {
                float a = arow[jj];
                e1 += a * vcol[jj * 256];
                ec += a * ecol[jj * 128];
            }
            size_t row = (size_t)(b * 64 + i);
            att[row * 512 + h2 * 128 + dd]       = e1;
            att[row * 512 + 256 + h2 * 128 + dd] = ec;
        }
    }
}

// ------------------------- mean pool ---------------------------------------
__global__ __launch_bounds__(128) void mean_kernel(
    const float* __restrict__ emb, float* __restrict__ out)
{
    int b = blockIdx.x, d = threadIdx.x;
    float s = 0.0f;
    #pragma unroll 4
    for (int n = 0; n < 64; n++) s += emb[((size_t)b * 64 + n) * Dm + d];
    out[b * Dm + d] = s * (1.0f / 64.0f);
}

// ---------------------------------------------------------------------------
extern "C" void kernel_launch(void* const* d_in, const int* in_sizes, int n_in,
                              void* d_out, int out_size)
{
    int mi = (in_sizes[3] == 262144) ? 3 : (n_in - 1);
    int wb = (mi == 3) ? 4 : 3;

    const float* node = (const float*)d_in[0];
    const float* stpe = (const float*)d_in[1];
    const float* edge = (const float*)d_in[2];
    const void*  mask = d_in[mi];
    const float* Wn   = (const float*)d_in[wb + 0];
    const float* bn   = (const float*)d_in[wb + 1];
    const float* We   = (const float*)d_in[wb + 2];
    const float* be   = (const float*)d_in[wb + 3];
    const float* ln1g = (const float*)d_in[wb + 4];
    const float* ln1b = (const float*)d_in[wb + 5];
    const float* Wq   = (const float*)d_in[wb + 6];
    const float* Wk   = (const float*)d_in[wb + 7];
    const float* Wv   = (const float*)d_in[wb + 8];
    const float* Wo   = (const float*)d_in[wb + 9];
    const float* bo   = (const float*)d_in[wb + 10];
    const float* ln2g = (const float*)d_in[wb + 11];
    const float* ln2b = (const float*)d_in[wb + 12];
    const float* W1   = (const float*)d_in[wb + 13];
    const float* b1   = (const float*)d_in[wb + 14];
    const float* W2   = (const float*)d_in[wb + 15];
    const float* b2   = (const float*)d_in[wb + 16];
    float* out = (float*)d_out;

    cudaFuncSetAttribute(attn3_kernel,
                         cudaFuncAttributeMaxDynamicSharedMemorySize, ATTN_SMEM);

    float *p_emb, *p_qkv, *p_att, *p_mid, *p_st, *p_Wqe, *p_Wce, *p_cvec;
    cudaGetSymbolAddress((void**)&p_emb,  g_emb);
    cudaGetSymbolAddress((void**)&p_qkv,  g_qkv);
    cudaGetSymbolAddress((void**)&p_att,  g_att);
    cudaGetSymbolAddress((void**)&p_mid,  g_mid);
    cudaGetSymbolAddress((void**)&p_st,   g_stats);
    cudaGetSymbolAddress((void**)&p_Wqe,  g_Wqe);
    cudaGetSymbolAddress((void**)&p_Wce,  g_Wce);
    cudaGetSymbolAddress((void**)&p_cvec, g_cvec);

    const int BIG = 1 << 20;

    detect_mask_kernel<<<1, 256>>>((const unsigned int*)mask);
    prep_wqe_kernel<<<dim3(128, Ll), 256>>>(Wq, We);
    prep_wce_kernel<<<dim3(256, Ll), 128>>>(We, Wo);
    prep_cvec_kernel<<<Ll, 128>>>(be, Wo, bo);

    // emb = cat(node, stpe) @ Wn + bn  (single GEMM, A split at k=128)
    gemmF<<<dim3(64, 2), 256>>>(node, stpe, 128, 128,
                                nullptr, nullptr, nullptr,
                                Wn, Wn, Wn, Wn, BIG, 128,
                                nullptr, BIG, 128,
                                bn, nullptr, 0,
                                p_emb, 128, 256, 0);

    for (int l = 0; l < Ll; l++) {
        // LN1 stats + fused QKV+QE projection (N=1024)
        ln_stats_kernel<<<512, 256>>>(p_emb, p_st, 1e-5f);
        gemmF<<<dim3(64, 16), 256>>>(p_emb, p_emb, BIG, 128,
                                     p_st, ln1g + l * 128, ln1b + l * 128,
                                     Wq + (size_t)l * 128 * 256,
                                     Wk + (size_t)l * 128 * 256,
                                     Wv + (size_t)l * 128 * 256,
                                     p_Wqe + (size_t)l * 128 * 256,
                                     256, 256,
                                     nullptr, BIG, 256,
                                     nullptr, nullptr, 0,
                                     p_qkv, 1024, 128, 0);

        attn3_kernel<<<dim3(64, 64 / TI), 256, ATTN_SMEM>>>(
            p_qkv, edge, be + l * 128, mask,
            out + 8192 + (size_t)l * 2 * 64 * 4096, p_att);

        // emb = [emb1cat | cecat] @ [Wo ; Wce] + cvec + residual  (K=512)
        gemmF<<<dim3(64, 2), 256>>>(p_att, p_att, BIG, 512,
                                    nullptr, nullptr, nullptr,
                                    Wo + (size_t)l * 256 * 128,
                                    Wo + (size_t)l * 256 * 128,
                                    Wo + (size_t)l * 256 * 128,
                                    Wo + (size_t)l * 256 * 128,
                                    BIG, 128,
                                    p_Wce + (size_t)l * 256 * 128, 256, 128,
                                    p_cvec + l * 128, p_emb, 128,
                                    p_emb, 128, 512, 0);

        // LN2 stats + FFN
        ln_stats_kernel<<<512, 256>>>(p_emb, p_st, 1e-6f);
        gemmF<<<dim3(64, 8), 256>>>(p_emb, p_emb, BIG, 128,
                                    p_st, ln2g + l * 128, ln2b + l * 128,
                                    W1 + (size_t)l * 128 * 512,
                                    W1 + (size_t)l * 128 * 512,
                                    W1 + (size_t)l * 128 * 512,
                                    W1 + (size_t)l * 128 * 512,
                                    BIG, 512,
                                    nullptr, BIG, 512,
                                    b1 + l * 512, nullptr, 0,
                                    p_mid, 512, 128, 1);
        gemmF<<<dim3(64, 2), 256>>>(p_mid, p_mid, BIG, 512,
                                    nullptr, nullptr, nullptr,
                                    W2 + (size_t)l * 512 * 128,
                                    W2 + (size_t)l * 512 * 128,
                                    W2 + (size_t)l * 512 * 128,
                                    W2 + (size_t)l * 512 * 128,
                                    BIG, 128,
                                    nullptr, BIG, 128,
                                    b2 + l * 128, p_emb, 128,
                                    p_emb, 128, 512, 0);
    }

    mean_kernel<<<64, 128>>>(p_emb, out);
}

// round 5
// speedup vs baseline: 1.9412x; 1.0972x over previous
#include <cuda_runtime.h>
#include <cuda_bf16.h>
#include <math.h>
#include <stdint.h>

// ---------------------------------------------------------------------------
// TGAN: 2-layer graph transformer with edge-bias attention.
// B=64, N=64, D=128, NH=2 (d_k=128), L=2.
//   bias = edge@We + be never materialized (folded into weights).
//   All GEMMs: BM=64 BN=128, f32x2 FFMA2 with duplicated-W smem (no MOVs).
//   N=128 GEMMs use split-K=2 over blockIdx.z; combine fused into LN-stats.
// ---------------------------------------------------------------------------

#define Bb 64
#define Nn 64
#define Dm 128
#define Ll 2
#define ROWS (Bb*Nn)          // 4096

typedef unsigned long long ull;

// ------------------------- scratch (device globals) ------------------------
__device__ float g_emb  [ROWS*Dm];
__device__ float g_p0   [ROWS*Dm];          // split-K partial 0
__device__ float g_p1   [ROWS*Dm];          // split-K partial 1
__device__ float g_qkv  [ROWS*1024];        // [q(256)|k(256)|v(256)|qe(256)]
__device__ float g_att  [ROWS*512];         // [emb1cat(256)|cecat(256)]
__device__ float g_mid  [ROWS*512];         // FFN mid
__device__ float g_stats[ROWS*2];           // (mu, rsig) per row
__device__ float g_Wqe  [Ll*128*256];       // Wqe[l][k][h*128+e]
__device__ float g_Wce  [Ll*256*128];       // Wce[l][h*128+e][n]
__device__ float g_cvec [Ll*128];
__device__ unsigned g_pf[64];               // mask dtype partial flags

// ------------------------- f32x2 helpers -----------------------------------
__device__ __forceinline__ ull ffma2(ull a, ull b, ull c) {
    ull d;
    asm("fma.rn.f32x2 %0, %1, %2, %3;" : "=l"(d) : "l"(a), "l"(b), "l"(c));
    return d;
}
__device__ __forceinline__ void unpack2(ull v, float& lo, float& hi) {
    unsigned a, b;
    asm("mov.b64 {%0, %1}, %2;" : "=r"(a), "=r"(b) : "l"(v));
    lo = __uint_as_float(a); hi = __uint_as_float(b);
}

__device__ __forceinline__ bool mask_at(const void* m, int idx, int mode) {
    if (mode == 0) return ((const int*)m)[idx] != 0;
    if (mode == 1) return ((const float*)m)[idx] != 0.0f;
    return ((const unsigned char*)m)[idx] != 0;
}

// ------------------------- prep (one launch, 577 blocks) --------------------
// [0,64): mask dtype partial flags     [64,320): Wqe
// [320,576): Wce                        576: cvec
__global__ __launch_bounds__(256) void prep_kernel(
    const unsigned* __restrict__ mask,
    const float* __restrict__ Wq, const float* __restrict__ We,
    const float* __restrict__ Wo, const float* __restrict__ be,
    const float* __restrict__ bo)
{
    const int bid = blockIdx.x, t = threadIdx.x;
    if (bid < 64) {
        __shared__ unsigned sfl;
        if (t == 0) sfl = 0;
        __syncthreads();
        unsigned f = 0;
        for (int p = bid * 1024 + t; p < (bid + 1) * 1024; p += 256) {
            unsigned w = mask[p];
            if (w > 1u) f |= 1u;
            if (w != 0u && w != 0x3F800000u) f |= 2u;
        }
        if (f) atomicOr(&sfl, f);
        __syncthreads();
        if (t == 0) g_pf[bid] = sfl;
    } else if (bid < 320) {
        // Wqe[l][k][he] = sum_d Wq[l][k][h*128+d] * We[l][e][d]
        int u = bid - 64, l = u >> 7, k = u & 127;
        __shared__ float wqrow[256];
        wqrow[t] = Wq[((size_t)l * 128 + k) * 256 + t];
        __syncthreads();
        int h = t >> 7, e = t & 127;
        const float* we = We + (size_t)l * 16384 + e * 128;
        const float* wq = wqrow + h * 128;
        float s = 0.0f;
        #pragma unroll 8
        for (int d = 0; d < 128; d++) s += wq[d] * we[d];
        g_Wqe[((size_t)l * 128 + k) * 256 + t] = s;
    } else if (bid < 576) {
        // Wce[l][he][n] = sum_d We[l][e][d] * Wo[l][h*128+d][n]
        int u = bid - 320, l = u >> 7, hp = (u & 127) * 2;
        __shared__ float weS[2][128];
        {
            int r = t >> 7, d = t & 127, he = hp + r, e = he & 127;
            weS[r][d] = We[(size_t)l * 16384 + e * 128 + d];
        }
        __syncthreads();
        int half = t >> 7, n = t & 127;
        int he = hp + half, h = he >> 7;
        const float* wo = Wo + (size_t)l * 32768 + (size_t)h * 128 * 128;
        float s = 0.0f;
        #pragma unroll 8
        for (int d = 0; d < 128; d++) s += weS[half][d] * wo[d * 128 + n];
        g_Wce[((size_t)l * 256 + he) * 128 + n] = s;
    } else {
        // cvec[l][n] = bo[n] + sum_d be[d]*(Wo[d][n] + Wo[128+d][n])
        int l = t >> 7, n = t & 127;
        const float* wo = Wo + (size_t)l * 32768;
        const float* bel = be + l * 128;
        float s = bo[l * 128 + n];
        #pragma unroll 8
        for (int d = 0; d < 128; d++)
            s += bel[d] * (wo[d * 128 + n] + wo[(128 + d) * 128 + n]);
        g_cvec[l * 128 + n] = s;
    }
}

// ------------------------- combine partials + LN stats ----------------------
// emb = p0 + p1; stats = (mu, rsqrt(var+eps)) per row. 512 blocks x 256.
__global__ __launch_bounds__(256) void combine_stats_kernel(
    const float* __restrict__ p0, const float* __restrict__ p1,
    float* __restrict__ emb, float* __restrict__ st, float eps)
{
    int row = blockIdx.x * 8 + (threadIdx.x >> 5);
    int lane = threadIdx.x & 31;
    float4 a = ((const float4*)(p0 + (size_t)row * 128))[lane];
    float4 b = ((const float4*)(p1 + (size_t)row * 128))[lane];
    float4 v; v.x = a.x + b.x; v.y = a.y + b.y; v.z = a.z + b.z; v.w = a.w + b.w;
    ((float4*)(emb + (size_t)row * 128))[lane] = v;
    float s = v.x + v.y + v.z + v.w;
    float q = v.x*v.x + v.y*v.y + v.z*v.z + v.w*v.w;
    #pragma unroll
    for (int o = 16; o; o >>= 1) {
        s += __shfl_xor_sync(0xffffffffu, s, o);
        q += __shfl_xor_sync(0xffffffffu, q, o);
    }
    if (lane == 0) {
        float mu = s * (1.0f / 128.0f);
        float var = q * (1.0f / 128.0f) - mu * mu;
        st[row * 2] = mu;
        st[row * 2 + 1] = rsqrtf(var + eps);
    }
}

// ------------------------- GEMM: BM=64 BN=128, f32x2 ------------------------
// C[M, n] = LN?(A)[M,K] @ W (+bias)(+res)(relu). blockIdx.z selects split-K
// half: z=0 uses A0/4-source W select/bias/res -> C0; z=1 uses A1/Wz1 -> C1.
__global__ __launch_bounds__(256) void gemmH(
    const float* __restrict__ A0, const float* __restrict__ A1, int sA,
    const float* __restrict__ lnst, const float* __restrict__ lng,
    const float* __restrict__ lnb,
    const float* __restrict__ Wp0, const float* __restrict__ Wp1,
    const float* __restrict__ Wp2, const float* __restrict__ Wp3,
    int wspan, int sW,
    const float* __restrict__ Wz1, int sWz1,
    const float* __restrict__ bias, const float* __restrict__ res, int sR,
    float* __restrict__ C0, float* __restrict__ C1, int sC,
    int K, int relu)
{
    __shared__ __align__(16) float AsT[16][68];
    __shared__ __align__(16) float WsD[16][256];   // duplicated W pairs

    const int m0 = blockIdx.x * 64, n0 = blockIdx.y * 128;
    const int z = blockIdx.z;
    const int t = threadIdx.x;
    const int lm = t >> 2, lk = (t & 3) * 4;       // A loader
    const int wk = t >> 4, wn8 = (t & 15) * 8;     // W loader
    const int tmi = t >> 5, tni = t & 31;          // compute

    const float* A = z ? A1 : A0;
    float* C = z ? C1 : C0;
    const float* Wb; int sWx, noffx;
    if (z) { Wb = Wz1; sWx = sWz1; noffx = n0; }
    else {
        int sel = n0 / wspan; noffx = n0 - sel * wspan;
        Wb = (sel == 0) ? Wp0 : (sel == 1) ? Wp1 : (sel == 2) ? Wp2 : Wp3;
        sWx = sW;
    }
    const float* biasx = z ? nullptr : bias;
    const float* resx  = z ? nullptr : res;

    float2 st = make_float2(0.0f, 1.0f);
    if (lnst) st = *(const float2*)(lnst + (size_t)(m0 + lm) * 2);

    ull acc[4][4];
    #pragma unroll
    for (int p = 0; p < 4; p++)
        #pragma unroll
        for (int j = 0; j < 4; j++) acc[p][j] = 0ull;

    auto loadA = [&](int k0) -> float4 {
        int kc = k0 + lk;
        float4 v = *(const float4*)&A[(size_t)(m0 + lm) * sA + kc];
        if (lnst) {
            float4 g4 = *(const float4*)(lng + kc);
            float4 b4 = *(const float4*)(lnb + kc);
            v.x = (v.x - st.x) * st.y * g4.x + b4.x;
            v.y = (v.y - st.x) * st.y * g4.y + b4.y;
            v.z = (v.z - st.x) * st.y * g4.z + b4.z;
            v.w = (v.w - st.x) * st.y * g4.w + b4.w;
        }
        return v;
    };

    float4 a = loadA(0);
    float4 w0 = *(const float4*)&Wb[(size_t)wk * sWx + noffx + wn8];
    float4 w1 = *(const float4*)&Wb[(size_t)wk * sWx + noffx + wn8 + 4];

    for (int k0 = 0; k0 < K; k0 += 16) {
        __syncthreads();
        AsT[lk+0][lm] = a.x; AsT[lk+1][lm] = a.y;
        AsT[lk+2][lm] = a.z; AsT[lk+3][lm] = a.w;
        float4 d0; d0.x = w0.x; d0.y = w0.x; d0.z = w0.y; d0.w = w0.y;
        float4 d1; d1.x = w0.z; d1.y = w0.z; d1.z = w0.w; d1.w = w0.w;
        float4 d2; d2.x = w1.x; d2.y = w1.x; d2.z = w1.y; d2.w = w1.y;
        float4 d3; d3.x = w1.z; d3.y = w1.z; d3.z = w1.w; d3.w = w1.w;
        *(float4*)&WsD[wk][wn8*2 +  0] = d0;
        *(float4*)&WsD[wk][wn8*2 +  4] = d1;
        *(float4*)&WsD[wk][wn8*2 +  8] = d2;
        *(float4*)&WsD[wk][wn8*2 + 12] = d3;
        __syncthreads();
        if (k0 + 16 < K) {
            a = loadA(k0 + 16);
            w0 = *(const float4*)&Wb[(size_t)(k0+16+wk) * sWx + noffx + wn8];
            w1 = *(const float4*)&Wb[(size_t)(k0+16+wk) * sWx + noffx + wn8 + 4];
        }
        #pragma unroll
        for (int kk = 0; kk < 16; kk++) {
            ulonglong2 a01 = *(const ulonglong2*)&AsT[kk][tmi*8];
            ulonglong2 a23 = *(const ulonglong2*)&AsT[kk][tmi*8 + 4];
            ulonglong2 v01 = *(const ulonglong2*)&WsD[kk][tni*8];
            ulonglong2 v23 = *(const ulonglong2*)&WsD[kk][tni*8 + 4];
            acc[0][0] = ffma2(a01.x, v01.x, acc[0][0]);
            acc[0][1] = ffma2(a01.x, v01.y, acc[0][1]);
            acc[0][2] = ffma2(a01.x, v23.x, acc[0][2]);
            acc[0][3] = ffma2(a01.x, v23.y, acc[0][3]);
            acc[1][0] = ffma2(a01.y, v01.x, acc[1][0]);
            acc[1][1] = ffma2(a01.y, v01.y, acc[1][1]);
            acc[1][2] = ffma2(a01.y, v23.x, acc[1][2]);
            acc[1][3] = ffma2(a01.y, v23.y, acc[1][3]);
            acc[2][0] = ffma2(a23.x, v01.x, acc[2][0]);
            acc[2][1] = ffma2(a23.x, v01.y, acc[2][1]);
            acc[2][2] = ffma2(a23.x, v23.x, acc[2][2]);
            acc[2][3] = ffma2(a23.x, v23.y, acc[2][3]);
            acc[3][0] = ffma2(a23.y, v01.x, acc[3][0]);
            acc[3][1] = ffma2(a23.y, v01.y, acc[3][1]);
            acc[3][2] = ffma2(a23.y, v23.x, acc[3][2]);
            acc[3][3] = ffma2(a23.y, v23.y, acc[3][3]);
        }
    }

    float o[8][4];
    #pragma unroll
    for (int p = 0; p < 4; p++)
        #pragma unroll
        for (int j = 0; j < 4; j++)
            unpack2(acc[p][j], o[2*p][j], o[2*p+1][j]);

    float4 bv = make_float4(0.f, 0.f, 0.f, 0.f);
    if (biasx) bv = *(const float4*)&biasx[n0 + tni * 4];
    #pragma unroll
    for (int rr = 0; rr < 8; rr++) {
        size_t row = (size_t)(m0 + tmi * 8 + rr);
        float4 ov;
        ov.x = o[rr][0] + bv.x; ov.y = o[rr][1] + bv.y;
        ov.z = o[rr][2] + bv.z; ov.w = o[rr][3] + bv.w;
        if (resx) {
            float4 r4 = *(const float4*)&resx[row * sR + n0 + tni * 4];
            ov.x += r4.x; ov.y += r4.y; ov.z += r4.z; ov.w += r4.w;
        }
        if (relu) {
            ov.x = fmaxf(ov.x, 0.f); ov.y = fmaxf(ov.y, 0.f);
            ov.z = fmaxf(ov.z, 0.f); ov.w = fmaxf(ov.w, 0.f);
        }
        *(float4*)&C[row * sC + n0 + tni * 4] = ov;
    }
}

// ------------------------- fused attention v4 (head-split) ------------------
// Block = (b, 16-row tile, head). smem ~50KB -> 4 blocks/SM, grid 512.
#define ATTN_SMEM ((8192 + 2048 + 2048 + 64 + 64 + 128 + 8 + 16 + 4) * 4)

__global__ __launch_bounds__(256) void attn4_kernel(
    const float* __restrict__ qkv, const float* __restrict__ edge,
    const float* __restrict__ be, const void* __restrict__ mask,
    float* __restrict__ aout, float* __restrict__ att)
{
    extern __shared__ float sm[];
    float* vsh  = sm;            // [64][128]
    float* qsh  = vsh + 8192;    // [16][128]
    float* qesh = qsh + 2048;    // [16][128]
    float* sraw = qesh + 2048;   // [64]
    float* sa   = sraw + 64;     // [64]
    float* bes  = sa + 64;       // [128]
    float* red  = bes + 128;     // [8]
    float* qbe  = red + 8;       // [16]
    unsigned* s_or = (unsigned*)(qbe + 16);  // [2]

    const int b = blockIdx.x, it0 = blockIdx.y * 16, h = blockIdx.z;
    const int t = threadIdx.x, w = t >> 5, lane = t & 31;
    const float4* qkv4 = (const float4*)qkv;
    const float4* edge4 = (const float4*)edge;

    // V head slice: cols 512 + h*128
    #pragma unroll
    for (int p = t; p < 2048; p += 256) {
        int j = p >> 5, dq = p & 31;
        ((float4*)vsh)[p] = qkv4[(size_t)(b*64 + j) * 256 + 128 + h*32 + dq];
    }
    // Q (cols h*128) and QE (cols 768 + h*128)
    #pragma unroll
    for (int p = t; p < 512; p += 256) {
        int r = p >> 5, dq = p & 31;
        ((float4*)qsh)[p]  = qkv4[(size_t)(b*64 + it0 + r) * 256 + h*32 + dq];
        ((float4*)qesh)[p] = qkv4[(size_t)(b*64 + it0 + r) * 256 + 192 + h*32 + dq];
    }
    if (t < 128) bes[t] = be[t];
    if (t < 64) {
        unsigned f = g_pf[t];
        #pragma unroll
        for (int o = 16; o; o >>= 1) f |= __shfl_xor_sync(0xffffffffu, f, o);
        if (lane == 0) s_or[w] = f;
    }
    __syncthreads();

    const unsigned fl = s_or[0] | s_or[1];
    const int mode = (!(fl & 1u)) ? 0 : ((!(fl & 2u)) ? 1 : 2);

    // qbe[ii] = q_row(ii) . be  (16 tasks over 8 warps)
    #pragma unroll
    for (int r = 0; r < 2; r++) {
        int ii = w * 2 + r;
        float4 q4 = ((const float4*)qsh)[ii * 32 + lane];
        float4 b4 = ((const float4*)bes)[lane];
        float s = q4.x*b4.x + q4.y*b4.y + q4.z*b4.z + q4.w*b4.w;
        #pragma unroll
        for (int o = 16; o; o >>= 1) s += __shfl_xor_sync(0xffffffffu, s, o);
        if (lane == 0) qbe[ii] = s;
    }

    const float invT = 0.0883883476483184405f;  // 1/sqrt(128)

    for (int ii = 0; ii < 16; ii++) {
        const int i = it0 + ii;
        // ---- scores: warp w handles j = w*8 .. w*8+7 ----
        {
            float4 q1 = ((const float4*)qsh)[ii * 32 + lane];
            float4 g1 = ((const float4*)qesh)[ii * 32 + lane];
            size_t erow0 = (size_t)(b * 64 + i) * 64;
            float s[8];
            #pragma unroll
            for (int r = 0; r < 8; r++) {
                int j = w * 8 + r;
                float4 ee = edge4[(erow0 + j) * 32 + lane];
                float4 kk = qkv4[(size_t)(b*64 + j) * 256 + 64 + h*32 + lane];
                s[r] = q1.x*kk.x + q1.y*kk.y + q1.z*kk.z + q1.w*kk.w
                     + g1.x*ee.x + g1.y*ee.y + g1.z*ee.z + g1.w*ee.w;
            }
            #pragma unroll
            for (int o = 16; o; o >>= 1) {
                #pragma unroll
                for (int r = 0; r < 8; r++)
                    s[r] += __shfl_xor_sync(0xffffffffu, s[r], o);
            }
            if (lane == 0) {
                #pragma unroll
                for (int r = 0; r < 8; r++) sraw[w * 8 + r] = s[r];
            }
        }
        __syncthreads();

        // ---- softmax over j (threads 0..63) ----
        float sc = 0.0f, ex = 0.0f;
        if (t < 64) {
            sc = (sraw[t] + qbe[ii]) * invT;
            if (mask_at(mask, ((b * 64 + i) << 6) + t, mode)) sc = 1e-10f;
            float m = sc;
            #pragma unroll
            for (int o = 16; o; o >>= 1)
                m = fmaxf(m, __shfl_xor_sync(0xffffffffu, m, o));
            if (lane == 0) red[w] = m;
        }
        __syncthreads();
        if (t < 64) {
            float hm = fmaxf(red[0], red[1]);
            ex = __expf(sc - hm);
            float ws = ex;
            #pragma unroll
            for (int o = 16; o; o >>= 1) ws += __shfl_xor_sync(0xffffffffu, ws, o);
            if (lane == 0) red[2 + w] = ws;
        }
        __syncthreads();
        if (t < 64) {
            float a = ex / (red[2] + red[3]);
            sa[t] = a;
            aout[((size_t)(h * 64 + b)) * 4096 + i * 64 + t] = a;
        }
        __syncthreads();

        // ---- emb1 = attn@V (smem), ce = attn@edge (global, cache-hot) ----
        if (t < 128) {
            const float* ecol = edge + (size_t)(b * 64 + i) * 8192 + t;
            float e1 = 0.0f, ec = 0.0f;
            #pragma unroll 8
            for (int jj = 0; jj < 64; jj++) {
                float a = sa[jj];
                e1 += a * vsh[jj * 128 + t];
                ec += a * ecol[jj * 128];
            }
            size_t row = (size_t)(b * 64 + i);
            att[row * 512 + h * 128 + t]       = e1;
            att[row * 512 + 256 + h * 128 + t] = ec;
        }
        __syncthreads();
    }
}

// ------------------------- final mean over partials -------------------------
__global__ __launch_bounds__(128) void mean_kernel(
    const float* __restrict__ p0, const float* __restrict__ p1,
    float* __restrict__ out)
{
    int b = blockIdx.x, d = threadIdx.x;
    float s = 0.0f;
    #pragma unroll 4
    for (int n = 0; n < 64; n++) {
        size_t idx = ((size_t)b * 64 + n) * 128 + d;
        s += p0[idx] + p1[idx];
    }
    out[b * 128 + d] = s * (1.0f / 64.0f);
}

// ---------------------------------------------------------------------------
extern "C" void kernel_launch(void* const* d_in, const int* in_sizes, int n_in,
                              void* d_out, int out_size)
{
    int mi = (in_sizes[3] == 262144) ? 3 : (n_in - 1);
    int wb = (mi == 3) ? 4 : 3;

    const float* node = (const float*)d_in[0];
    const float* stpe = (const float*)d_in[1];
    const float* edge = (const float*)d_in[2];
    const void*  mask = d_in[mi];
    const float* Wn   = (const float*)d_in[wb + 0];
    const float* bn   = (const float*)d_in[wb + 1];
    const float* We   = (const float*)d_in[wb + 2];
    const float* be   = (const float*)d_in[wb + 3];
    const float* ln1g = (const float*)d_in[wb + 4];
    const float* ln1b = (const float*)d_in[wb + 5];
    const float* Wq   = (const float*)d_in[wb + 6];
    const float* Wk   = (const float*)d_in[wb + 7];
    const float* Wv   = (const float*)d_in[wb + 8];
    const float* Wo   = (const float*)d_in[wb + 9];
    const float* bo   = (const float*)d_in[wb + 10];
    const float* ln2g = (const float*)d_in[wb + 11];
    const float* ln2b = (const float*)d_in[wb + 12];
    const float* W1   = (const float*)d_in[wb + 13];
    const float* b1   = (const float*)d_in[wb + 14];
    const float* W2   = (const float*)d_in[wb + 15];
    const float* b2   = (const float*)d_in[wb + 16];
    float* out = (float*)d_out;

    cudaFuncSetAttribute(attn4_kernel,
                         cudaFuncAttributeMaxDynamicSharedMemorySize, ATTN_SMEM);

    float *p_emb, *p_p0, *p_p1, *p_qkv, *p_att, *p_mid, *p_st,
          *p_Wqe, *p_Wce, *p_cvec;
    cudaGetSymbolAddress((void**)&p_emb,  g_emb);
    cudaGetSymbolAddress((void**)&p_p0,   g_p0);
    cudaGetSymbolAddress((void**)&p_p1,   g_p1);
    cudaGetSymbolAddress((void**)&p_qkv,  g_qkv);
    cudaGetSymbolAddress((void**)&p_att,  g_att);
    cudaGetSymbolAddress((void**)&p_mid,  g_mid);
    cudaGetSymbolAddress((void**)&p_st,   g_stats);
    cudaGetSymbolAddress((void**)&p_Wqe,  g_Wqe);
    cudaGetSymbolAddress((void**)&p_Wce,  g_Wce);
    cudaGetSymbolAddress((void**)&p_cvec, g_cvec);

    const int BIG = 1 << 20;

    // one-shot prep: mask partials + folded weights
    prep_kernel<<<577, 256>>>((const unsigned*)mask, Wq, We, Wo, be, bo);

    // emb partials: z0 = node@Wn[0:128]+bn, z1 = stpe@Wn[128:256]
    gemmH<<<dim3(64, 1, 2), 256>>>(
        node, stpe, 128,
        nullptr, nullptr, nullptr,
        Wn, Wn, Wn, Wn, BIG, 128,
        Wn + 128 * 128, 128,
        bn, nullptr, 0,
        p_p0, p_p1, 128, 128, 0);

    for (int l = 0; l < Ll; l++) {
        // combine previous partials -> emb, + LN1 stats (eps 1e-5)
        combine_stats_kernel<<<512, 256>>>(p_p0, p_p1, p_emb, p_st, 1e-5f);

        // fused QKV+QE projection (N=1024, 512 blocks)
        gemmH<<<dim3(64, 8, 1), 256>>>(
            p_emb, nullptr, 128,
            p_st, ln1g + l * 128, ln1b + l * 128,
            Wq + (size_t)l * 128 * 256, Wk + (size_t)l * 128 * 256,
            Wv + (size_t)l * 128 * 256, p_Wqe + (size_t)l * 128 * 256,
            256, 256,
            nullptr, 0,
            nullptr, nullptr, 0,
            p_qkv, nullptr, 1024, 128, 0);

        // attention (head-split, 512 blocks)
        attn4_kernel<<<dim3(64, 4, 2), 256, ATTN_SMEM>>>(
            p_qkv, edge, be + l * 128, mask,
            out + 8192 + (size_t)l * 2 * 64 * 4096, p_att);

        // output proj split-K: z0 = emb1cat@Wo + cvec + residual,
        //                      z1 = cecat@Wce
        gemmH<<<dim3(64, 1, 2), 256>>>(
            p_att, p_att + 256, 512,
            nullptr, nullptr, nullptr,
            Wo + (size_t)l * 256 * 128, nullptr, nullptr, nullptr, BIG, 128,
            p_Wce + (size_t)l * 256 * 128, 128,
            p_cvec + l * 128, p_emb, 128,
            p_p0, p_p1, 128, 256, 0);

        // combine -> emb, + LN2 stats (eps 1e-6)
        combine_stats_kernel<<<512, 256>>>(p_p0, p_p1, p_emb, p_st, 1e-6f);

        // FFN1 (N=512, 256 blocks), LN-fused, relu
        gemmH<<<dim3(64, 4, 1), 256>>>(
            p_emb, nullptr, 128,
            p_st, ln2g + l * 128, ln2b + l * 128,
            W1 + (size_t)l * 128 * 512, nullptr, nullptr, nullptr, BIG, 512,
            nullptr, 0,
            b1 + l * 512, nullptr, 0,
            p_mid, nullptr, 512, 128, 1);

        // FFN2 split-K: z0 = mid[:,0:256]@W2[0:256] + b2 + residual,
        //               z1 = mid[:,256:512]@W2[256:512]
        gemmH<<<dim3(64, 1, 2), 256>>>(
            p_mid, p_mid + 256, 512,
            nullptr, nullptr, nullptr,
            W2 + (size_t)l * 512 * 128, nullptr, nullptr, nullptr, BIG, 128,
            W2 + (size_t)l * 512 * 128 + 256 * 128, 128,
            b2 + l * 128, p_emb, 128,
            p_p0, p_p1, 128, 256, 0);
    }

    mean_kernel<<<64, 128>>>(p_p0, p_p1, out);
}

// round 6
// speedup vs baseline: 2.3751x; 1.2235x over previous
#include <cuda_runtime.h>
#include <math.h>
#include <stdint.h>

// ---------------------------------------------------------------------------
// TGAN: 2-layer graph transformer with edge-bias attention.
// B=64, N=64, D=128, NH=2 (d_k=128), L=2.
//   bias = edge@We + be never materialized (folded into weights).
//   gemmK: 128thr, BM64/BN128, 8x8/thread, f32x2 FFMA2 + mov-broadcast,
//          cp.async double-buffered W, LN fused into A loads.
//   All GEMM K == 128 (split-K=4 where needed, combine fused into LN stats).
// ---------------------------------------------------------------------------

#define Ll 2
#define ROWS 4096

typedef unsigned long long ull;

// ------------------------- scratch (device globals) ------------------------
__device__ float g_emb [ROWS*128];
__device__ float g_p0  [ROWS*128];
__device__ float g_p1  [ROWS*128];
__device__ float g_p2  [ROWS*128];
__device__ float g_p3  [ROWS*128];
__device__ float g_zero[ROWS*128];      // never written: stays zero
__device__ float g_qkv [ROWS*1024];     // [q(256)|k(256)|v(256)|qe(256)]
__device__ float g_att [ROWS*512];      // [emb1cat(256)|cecat(256)]
__device__ float g_mid [ROWS*512];
__device__ float g_stats[ROWS*2];
__device__ float g_Wqe [Ll*128*256];
__device__ float g_Wce [Ll*256*128];
__device__ float g_cvec[Ll*128];
__device__ unsigned g_pf[64];

// ------------------------- helpers -----------------------------------------
__device__ __forceinline__ ull ffma2(ull a, ull b, ull c) {
    ull d;
    asm("fma.rn.f32x2 %0, %1, %2, %3;" : "=l"(d) : "l"(a), "l"(b), "l"(c));
    return d;
}
__device__ __forceinline__ ull bcast2(float x) {
    ull d;
    asm("mov.b64 %0, {%1, %1};" : "=l"(d) : "r"(__float_as_uint(x)));
    return d;
}
__device__ __forceinline__ void unpack2(ull v, float& lo, float& hi) {
    unsigned a, b;
    asm("mov.b64 {%0, %1}, %2;" : "=r"(a), "=r"(b) : "l"(v));
    lo = __uint_as_float(a); hi = __uint_as_float(b);
}
__device__ __forceinline__ bool mask_at(const void* m, int idx, int mode) {
    if (mode == 0) return ((const int*)m)[idx] != 0;
    if (mode == 1) return ((const float*)m)[idx] != 0.0f;
    return ((const unsigned char*)m)[idx] != 0;
}

// ------------------------- prep (one launch, 577 blocks) --------------------
__global__ __launch_bounds__(256) void prep_kernel(
    const unsigned* __restrict__ mask,
    const float* __restrict__ Wq, const float* __restrict__ We,
    const float* __restrict__ Wo, const float* __restrict__ be,
    const float* __restrict__ bo)
{
    const int bid = blockIdx.x, t = threadIdx.x;
    if (bid < 64) {
        __shared__ unsigned sfl;
        if (t == 0) sfl = 0;
        __syncthreads();
        unsigned f = 0;
        for (int p = bid * 1024 + t; p < (bid + 1) * 1024; p += 256) {
            unsigned w = mask[p];
            if (w > 1u) f |= 1u;
            if (w != 0u && w != 0x3F800000u) f |= 2u;
        }
        if (f) atomicOr(&sfl, f);
        __syncthreads();
        if (t == 0) g_pf[bid] = sfl;
    } else if (bid < 320) {
        int u = bid - 64, l = u >> 7, k = u & 127;
        __shared__ float wqrow[256];
        wqrow[t] = Wq[((size_t)l * 128 + k) * 256 + t];
        __syncthreads();
        int h = t >> 7, e = t & 127;
        const float* we = We + (size_t)l * 16384 + e * 128;
        const float* wq = wqrow + h * 128;
        float s = 0.0f;
        #pragma unroll 8
        for (int d = 0; d < 128; d++) s += wq[d] * we[d];
        g_Wqe[((size_t)l * 128 + k) * 256 + t] = s;
    } else if (bid < 576) {
        int u = bid - 320, l = u >> 7, hp = (u & 127) * 2;
        __shared__ float weS[2][128];
        {
            int r = t >> 7, d = t & 127, he = hp + r, e = he & 127;
            weS[r][d] = We[(size_t)l * 16384 + e * 128 + d];
        }
        __syncthreads();
        int half = t >> 7, n = t & 127;
        int he = hp + half, h = he >> 7;
        const float* wo = Wo + (size_t)l * 32768 + (size_t)h * 128 * 128;
        float s = 0.0f;
        #pragma unroll 8
        for (int d = 0; d < 128; d++) s += weS[half][d] * wo[d * 128 + n];
        g_Wce[((size_t)l * 256 + he) * 128 + n] = s;
    } else {
        int l = t >> 7, n = t & 127;
        const float* wo = Wo + (size_t)l * 32768;
        const float* bel = be + l * 128;
        float s = bo[l * 128 + n];
        #pragma unroll 8
        for (int d = 0; d < 128; d++)
            s += bel[d] * (wo[d * 128 + n] + wo[(128 + d) * 128 + n]);
        g_cvec[l * 128 + n] = s;
    }
}

// ------------------------- combine 4 partials + LN stats --------------------
__global__ __launch_bounds__(256) void combine4_kernel(
    const float* __restrict__ p0, const float* __restrict__ p1,
    const float* __restrict__ p2, const float* __restrict__ p3,
    float* __restrict__ emb, float* __restrict__ st, float eps)
{
    int row = blockIdx.x * 8 + (threadIdx.x >> 5);
    int lane = threadIdx.x & 31;
    float4 a = ((const float4*)(p0 + (size_t)row * 128))[lane];
    float4 b = ((const float4*)(p1 + (size_t)row * 128))[lane];
    float4 c = ((const float4*)(p2 + (size_t)row * 128))[lane];
    float4 d = ((const float4*)(p3 + (size_t)row * 128))[lane];
    float4 v;
    v.x = (a.x + b.x) + (c.x + d.x); v.y = (a.y + b.y) + (c.y + d.y);
    v.z = (a.z + b.z) + (c.z + d.z); v.w = (a.w + b.w) + (c.w + d.w);
    ((float4*)(emb + (size_t)row * 128))[lane] = v;
    float s = v.x + v.y + v.z + v.w;
    float q = v.x*v.x + v.y*v.y + v.z*v.z + v.w*v.w;
    #pragma unroll
    for (int o = 16; o; o >>= 1) {
        s += __shfl_xor_sync(0xffffffffu, s, o);
        q += __shfl_xor_sync(0xffffffffu, q, o);
    }
    if (lane == 0) {
        float mu = s * (1.0f / 128.0f);
        float var = q * (1.0f / 128.0f) - mu * mu;
        st[row * 2] = mu;
        st[row * 2 + 1] = rsqrtf(var + eps);
    }
}

// ------------------------- gemmK: BM=64 BN=128, 128 threads, 8x8 ------------
// K must be 128. z==0: n-select W among Wp0..3 (wspan), bias/res allowed.
// z>0: A/W/C from z-indexed args, no bias/res (split-K partials).
__global__ __launch_bounds__(128) void gemmK(
    const float* __restrict__ A0, const float* __restrict__ A1,
    const float* __restrict__ A2, const float* __restrict__ A3, int sA,
    const float* __restrict__ lnst, const float* __restrict__ lng,
    const float* __restrict__ lnb,
    const float* __restrict__ Wp0, const float* __restrict__ Wp1,
    const float* __restrict__ Wp2, const float* __restrict__ Wp3,
    int wspan, int sW,
    const float* __restrict__ Wz1, const float* __restrict__ Wz2,
    const float* __restrict__ Wz3, int sWz,
    const float* __restrict__ bias, const float* __restrict__ res, int sR,
    float* __restrict__ C0, float* __restrict__ C1,
    float* __restrict__ C2, float* __restrict__ C3, int sC, int relu)
{
    __shared__ __align__(16) float AsT[2][16][68];
    __shared__ __align__(16) float Wsm[2][16][128];

    const int m0 = blockIdx.x * 64, n0 = blockIdx.y * 128;
    const int z = blockIdx.z;
    const int t = threadIdx.x;
    const int ar = t & 63, ak = (t >> 6) * 8;      // A loader
    const int wkr = t >> 3, wnc = (t & 7) * 16;    // W loader (cp.async)
    const int tmi = t >> 4, tni = t & 15;          // compute: m=tmi*8, n=tni*8

    const float *A, *W; float* C;
    const float *biasx, *resx;
    int sWx;
    if (z == 0) {
        A = A0; C = C0;
        int sel = n0 / wspan;
        W = ((sel == 0) ? Wp0 : (sel == 1) ? Wp1 : (sel == 2) ? Wp2 : Wp3)
            + (n0 - sel * wspan);
        sWx = sW; biasx = bias; resx = res;
    } else {
        A = (z == 1) ? A1 : (z == 2) ? A2 : A3;
        W = ((z == 1) ? Wz1 : (z == 2) ? Wz2 : Wz3) + n0;
        C = (z == 1) ? C1 : (z == 2) ? C2 : C3;
        sWx = sWz; biasx = nullptr; resx = nullptr;
    }

    const bool doLN = (lnst != nullptr);
    float2 st = make_float2(0.0f, 1.0f);
    if (doLN) st = *(const float2*)(lnst + (size_t)(m0 + ar) * 2);

    const uint32_t wsm_base = (uint32_t)__cvta_generic_to_shared(&Wsm[0][0][0]);

    auto issueW = [&](int k0, int buf) {
        const float* src = W + (size_t)(k0 + wkr) * sWx + wnc;
        uint32_t dst = wsm_base + (uint32_t)(((buf * 16 + wkr) * 128 + wnc) * 4);
        #pragma unroll
        for (int i = 0; i < 4; i++)
            asm volatile("cp.async.cg.shared.global [%0], [%1], 16;"
                         :: "r"(dst + i * 16), "l"(src + i * 4));
        asm volatile("cp.async.commit_group;");
    };
    auto loadA = [&](int k0, float4& va, float4& vb) {
        const float* p = A + (size_t)(m0 + ar) * sA + k0 + ak;
        va = *(const float4*)p; vb = *(const float4*)(p + 4);
        if (doLN) {
            float4 g0 = *(const float4*)(lng + k0 + ak);
            float4 g1 = *(const float4*)(lng + k0 + ak + 4);
            float4 b0 = *(const float4*)(lnb + k0 + ak);
            float4 b1 = *(const float4*)(lnb + k0 + ak + 4);
            va.x = (va.x - st.x) * st.y * g0.x + b0.x;
            va.y = (va.y - st.x) * st.y * g0.y + b0.y;
            va.z = (va.z - st.x) * st.y * g0.z + b0.z;
            va.w = (va.w - st.x) * st.y * g0.w + b0.w;
            vb.x = (vb.x - st.x) * st.y * g1.x + b1.x;
            vb.y = (vb.y - st.x) * st.y * g1.y + b1.y;
            vb.z = (vb.z - st.x) * st.y * g1.z + b1.z;
            vb.w = (vb.w - st.x) * st.y * g1.w + b1.w;
        }
    };

    ull acc[4][8];
    #pragma unroll
    for (int p = 0; p < 4; p++)
        #pragma unroll
        for (int j = 0; j < 8; j++) acc[p][j] = 0ull;

    issueW(0, 0);
    float4 a0, a1;
    loadA(0, a0, a1);

    const int S = 8;  // K = 128
    #pragma unroll 2
    for (int s = 0; s < S; s++) {
        const int buf = s & 1;
        AsT[buf][ak+0][ar] = a0.x; AsT[buf][ak+1][ar] = a0.y;
        AsT[buf][ak+2][ar] = a0.z; AsT[buf][ak+3][ar] = a0.w;
        AsT[buf][ak+4][ar] = a1.x; AsT[buf][ak+5][ar] = a1.y;
        AsT[buf][ak+6][ar] = a1.z; AsT[buf][ak+7][ar] = a1.w;
        asm volatile("cp.async.wait_group 0;");
        __syncthreads();
        if (s + 1 < S) {
            issueW((s + 1) << 4, buf ^ 1);
            loadA((s + 1) << 4, a0, a1);
        }
        #pragma unroll
        for (int kk = 0; kk < 16; kk++) {
            ulonglong2 A01 = *(const ulonglong2*)&AsT[buf][kk][tmi * 8];
            ulonglong2 A23 = *(const ulonglong2*)&AsT[buf][kk][tmi * 8 + 4];
            float4 w0 = *(const float4*)&Wsm[buf][kk][tni * 8];
            float4 w1 = *(const float4*)&Wsm[buf][kk][tni * 8 + 4];
            ull aa[4] = {A01.x, A01.y, A23.x, A23.y};
            ull bb[8] = {bcast2(w0.x), bcast2(w0.y), bcast2(w0.z), bcast2(w0.w),
                         bcast2(w1.x), bcast2(w1.y), bcast2(w1.z), bcast2(w1.w)};
            #pragma unroll
            for (int p = 0; p < 4; p++)
                #pragma unroll
                for (int j = 0; j < 8; j++)
                    acc[p][j] = ffma2(aa[p], bb[j], acc[p][j]);
        }
        __syncthreads();
    }

    float4 bv0 = make_float4(0.f, 0.f, 0.f, 0.f), bv1 = bv0;
    if (biasx) {
        bv0 = *(const float4*)&biasx[n0 + tni * 8];
        bv1 = *(const float4*)&biasx[n0 + tni * 8 + 4];
    }
    #pragma unroll
    for (int p = 0; p < 4; p++) {
        float lo[8], hi[8];
        #pragma unroll
        for (int j = 0; j < 8; j++) unpack2(acc[p][j], lo[j], hi[j]);
        #pragma unroll
        for (int r = 0; r < 2; r++) {
            float* o = r ? hi : lo;
            size_t row = (size_t)(m0 + tmi * 8 + p * 2 + r);
            float4 o0, o1;
            o0.x = o[0] + bv0.x; o0.y = o[1] + bv0.y;
            o0.z = o[2] + bv0.z; o0.w = o[3] + bv0.w;
            o1.x = o[4] + bv1.x; o1.y = o[5] + bv1.y;
            o1.z = o[6] + bv1.z; o1.w = o[7] + bv1.w;
            if (resx) {
                float4 r0 = *(const float4*)&resx[row * sR + n0 + tni * 8];
                float4 r1 = *(const float4*)&resx[row * sR + n0 + tni * 8 + 4];
                o0.x += r0.x; o0.y += r0.y; o0.z += r0.z; o0.w += r0.w;
                o1.x += r1.x; o1.y += r1.y; o1.z += r1.z; o1.w += r1.w;
            }
            if (relu) {
                o0.x = fmaxf(o0.x, 0.f); o0.y = fmaxf(o0.y, 0.f);
                o0.z = fmaxf(o0.z, 0.f); o0.w = fmaxf(o0.w, 0.f);
                o1.x = fmaxf(o1.x, 0.f); o1.y = fmaxf(o1.y, 0.f);
                o1.z = fmaxf(o1.z, 0.f); o1.w = fmaxf(o1.w, 0.f);
            }
            *(float4*)&C[row * sC + n0 + tni * 8]     = o0;
            *(float4*)&C[row * sC + n0 + tni * 8 + 4] = o1;
        }
    }
}

// ------------------------- fused attention v4 (head-split) ------------------
#define ATTN_SMEM ((8192 + 2048 + 2048 + 64 + 64 + 128 + 8 + 16 + 4) * 4)

__global__ __launch_bounds__(256) void attn4_kernel(
    const float* __restrict__ qkv, const float* __restrict__ edge,
    const float* __restrict__ be, const void* __restrict__ mask,
    float* __restrict__ aout, float* __restrict__ att)
{
    extern __shared__ float sm[];
    float* vsh  = sm;            // [64][128]
    float* qsh  = vsh + 8192;    // [16][128]
    float* qesh = qsh + 2048;    // [16][128]
    float* sraw = qesh + 2048;   // [64]
    float* sa   = sraw + 64;     // [64]
    float* bes  = sa + 64;       // [128]
    float* red  = bes + 128;     // [8]
    float* qbe  = red + 8;       // [16]
    unsigned* s_or = (unsigned*)(qbe + 16);

    const int b = blockIdx.x, it0 = blockIdx.y * 16, h = blockIdx.z;
    const int t = threadIdx.x, w = t >> 5, lane = t & 31;
    const float4* qkv4 = (const float4*)qkv;
    const float4* edge4 = (const float4*)edge;

    #pragma unroll
    for (int p = t; p < 2048; p += 256) {
        int j = p >> 5, dq = p & 31;
        ((float4*)vsh)[p] = qkv4[(size_t)(b*64 + j) * 256 + 128 + h*32 + dq];
    }
    #pragma unroll
    for (int p = t; p < 512; p += 256) {
        int r = p >> 5, dq = p & 31;
        ((float4*)qsh)[p]  = qkv4[(size_t)(b*64 + it0 + r) * 256 + h*32 + dq];
        ((float4*)qesh)[p] = qkv4[(size_t)(b*64 + it0 + r) * 256 + 192 + h*32 + dq];
    }
    if (t < 128) bes[t] = be[t];
    if (t < 64) {
        unsigned f = g_pf[t];
        #pragma unroll
        for (int o = 16; o; o >>= 1) f |= __shfl_xor_sync(0xffffffffu, f, o);
        if (lane == 0) s_or[w] = f;
    }
    __syncthreads();

    const unsigned fl = s_or[0] | s_or[1];
    const int mode = (!(fl & 1u)) ? 0 : ((!(fl & 2u)) ? 1 : 2);

    #pragma unroll
    for (int r = 0; r < 2; r++) {
        int ii = w * 2 + r;
        float4 q4 = ((const float4*)qsh)[ii * 32 + lane];
        float4 b4 = ((const float4*)bes)[lane];
        float s = q4.x*b4.x + q4.y*b4.y + q4.z*b4.z + q4.w*b4.w;
        #pragma unroll
        for (int o = 16; o; o >>= 1) s += __shfl_xor_sync(0xffffffffu, s, o);
        if (lane == 0) qbe[ii] = s;
    }

    const float invT = 0.0883883476483184405f;

    for (int ii = 0; ii < 16; ii++) {
        const int i = it0 + ii;
        {
            float4 q1 = ((const float4*)qsh)[ii * 32 + lane];
            float4 g1 = ((const float4*)qesh)[ii * 32 + lane];
            size_t erow0 = (size_t)(b * 64 + i) * 64;
            float s[8];
            #pragma unroll
            for (int r = 0; r < 8; r++) {
                int j = w * 8 + r;
                float4 ee = edge4[(erow0 + j) * 32 + lane];
                float4 kk = qkv4[(size_t)(b*64 + j) * 256 + 64 + h*32 + lane];
                s[r] = q1.x*kk.x + q1.y*kk.y + q1.z*kk.z + q1.w*kk.w
                     + g1.x*ee.x + g1.y*ee.y + g1.z*ee.z + g1.w*ee.w;
            }
            #pragma unroll
            for (int o = 16; o; o >>= 1) {
                #pragma unroll
                for (int r = 0; r < 8; r++)
                    s[r] += __shfl_xor_sync(0xffffffffu, s[r], o);
            }
            if (lane == 0) {
                #pragma unroll
                for (int r = 0; r < 8; r++) sraw[w * 8 + r] = s[r];
            }
        }
        __syncthreads();

        float sc = 0.0f, ex = 0.0f;
        if (t < 64) {
            sc = (sraw[t] + qbe[ii]) * invT;
            if (mask_at(mask, ((b * 64 + i) << 6) + t, mode)) sc = 1e-10f;
            float m = sc;
            #pragma unroll
            for (int o = 16; o; o >>= 1)
                m = fmaxf(m, __shfl_xor_sync(0xffffffffu, m, o));
            if (lane == 0) red[w] = m;
        }
        __syncthreads();
        if (t < 64) {
            float hm = fmaxf(red[0], red[1]);
            ex = __expf(sc - hm);
            float ws = ex;
            #pragma unroll
            for (int o = 16; o; o >>= 1) ws += __shfl_xor_sync(0xffffffffu, ws, o);
            if (lane == 0) red[2 + w] = ws;
        }
        __syncthreads();
        if (t < 64) {
            float a = ex / (red[2] + red[3]);
            sa[t] = a;
            aout[((size_t)(h * 64 + b)) * 4096 + i * 64 + t] = a;
        }
        __syncthreads();

        if (t < 128) {
            const float* ecol = edge + (size_t)(b * 64 + i) * 8192 + t;
            float e1 = 0.0f, ec = 0.0f;
            #pragma unroll 8
            for (int jj = 0; jj < 64; jj++) {
                float a = sa[jj];
                e1 += a * vsh[jj * 128 + t];
                ec += a * ecol[jj * 128];
            }
            size_t row = (size_t)(b * 64 + i);
            att[row * 512 + h * 128 + t]       = e1;
            att[row * 512 + 256 + h * 128 + t] = ec;
        }
        __syncthreads();
    }
}

// ------------------------- final mean over 4 partials -----------------------
__global__ __launch_bounds__(128) void mean4_kernel(
    const float* __restrict__ p0, const float* __restrict__ p1,
    const float* __restrict__ p2, const float* __restrict__ p3,
    float* __restrict__ out)
{
    int b = blockIdx.x, d = threadIdx.x;
    float s = 0.0f;
    #pragma unroll 4
    for (int n = 0; n < 64; n++) {
        size_t idx = ((size_t)b * 64 + n) * 128 + d;
        s += (p0[idx] + p1[idx]) + (p2[idx] + p3[idx]);
    }
    out[b * 128 + d] = s * (1.0f / 64.0f);
}

// ---------------------------------------------------------------------------
extern "C" void kernel_launch(void* const* d_in, const int* in_sizes, int n_in,
                              void* d_out, int out_size)
{
    int mi = (in_sizes[3] == 262144) ? 3 : (n_in - 1);
    int wb = (mi == 3) ? 4 : 3;

    const float* node = (const float*)d_in[0];
    const float* stpe = (const float*)d_in[1];
    const float* edge = (const float*)d_in[2];
    const void*  mask = d_in[mi];
    const float* Wn   = (const float*)d_in[wb + 0];
    const float* bn   = (const float*)d_in[wb + 1];
    const float* We   = (const float*)d_in[wb + 2];
    const float* be   = (const float*)d_in[wb + 3];
    const float* ln1g = (const float*)d_in[wb + 4];
    const float* ln1b = (const float*)d_in[wb + 5];
    const float* Wq   = (const float*)d_in[wb + 6];
    const float* Wk   = (const float*)d_in[wb + 7];
    const float* Wv   = (const float*)d_in[wb + 8];
    const float* Wo   = (const float*)d_in[wb + 9];
    const float* bo   = (const float*)d_in[wb + 10];
    const float* ln2g = (const float*)d_in[wb + 11];
    const float* ln2b = (const float*)d_in[wb + 12];
    const float* W1   = (const float*)d_in[wb + 13];
    const float* b1   = (const float*)d_in[wb + 14];
    const float* W2   = (const float*)d_in[wb + 15];
    const float* b2   = (const float*)d_in[wb + 16];
    float* out = (float*)d_out;

    cudaFuncSetAttribute(attn4_kernel,
                         cudaFuncAttributeMaxDynamicSharedMemorySize, ATTN_SMEM);

    float *p_emb, *p_p0, *p_p1, *p_p2, *p_p3, *p_zero, *p_qkv, *p_att,
          *p_mid, *p_st, *p_Wqe, *p_Wce, *p_cvec;
    cudaGetSymbolAddress((void**)&p_emb,  g_emb);
    cudaGetSymbolAddress((void**)&p_p0,   g_p0);
    cudaGetSymbolAddress((void**)&p_p1,   g_p1);
    cudaGetSymbolAddress((void**)&p_p2,   g_p2);
    cudaGetSymbolAddress((void**)&p_p3,   g_p3);
    cudaGetSymbolAddress((void**)&p_zero, g_zero);
    cudaGetSymbolAddress((void**)&p_qkv,  g_qkv);
    cudaGetSymbolAddress((void**)&p_att,  g_att);
    cudaGetSymbolAddress((void**)&p_mid,  g_mid);
    cudaGetSymbolAddress((void**)&p_st,   g_stats);
    cudaGetSymbolAddress((void**)&p_Wqe,  g_Wqe);
    cudaGetSymbolAddress((void**)&p_Wce,  g_Wce);
    cudaGetSymbolAddress((void**)&p_cvec, g_cvec);

    const int BIG = 1 << 20;

    prep_kernel<<<577, 256>>>((const unsigned*)mask, Wq, We, Wo, be, bo);

    // emb partials: z0 = node@Wn[0:128]+bn -> p0, z1 = stpe@Wn[128:256] -> p1
    gemmK<<<dim3(64, 1, 2), 128>>>(
        node, stpe, stpe, stpe, 128,
        nullptr, nullptr, nullptr,
        Wn, Wn, Wn, Wn, BIG, 128,
        Wn + 128 * 128, Wn + 128 * 128, Wn + 128 * 128, 128,
        bn, nullptr, 0,
        p_p0, p_p1, p_p1, p_p1, 128, 0);

    const float* prev2 = p_zero;  // partials 2,3 of previous stage
    const float* prev3 = p_zero;

    for (int l = 0; l < Ll; l++) {
        // combine -> emb, LN1 stats (eps 1e-5)
        combine4_kernel<<<512, 256>>>(p_p0, p_p1, prev2, prev3,
                                      p_emb, p_st, 1e-5f);

        // fused QKV+QE projection (N=1024, grid 512)
        gemmK<<<dim3(64, 8, 1), 128>>>(
            p_emb, p_emb, p_emb, p_emb, 128,
            p_st, ln1g + l * 128, ln1b + l * 128,
            Wq + (size_t)l * 128 * 256, Wk + (size_t)l * 128 * 256,
            Wv + (size_t)l * 128 * 256, p_Wqe + (size_t)l * 128 * 256,
            256, 256,
            nullptr, nullptr, nullptr, 0,
            nullptr, nullptr, 0,
            p_qkv, nullptr, nullptr, nullptr, 1024, 0);

        // attention (head-split, 512 blocks)
        attn4_kernel<<<dim3(64, 4, 2), 256, ATTN_SMEM>>>(
            p_qkv, edge, be + l * 128, mask,
            out + 8192 + (size_t)l * 2 * 64 * 4096, p_att);

        // output proj split-K=4:
        //  z0: att[:,0:128]@Wo[0:128] + cvec + emb -> p0
        //  z1: att[:,128:256]@Wo[128:256] -> p1
        //  z2: att[:,256:384]@Wce[0:128] -> p2
        //  z3: att[:,384:512]@Wce[128:256] -> p3
        gemmK<<<dim3(64, 1, 4), 128>>>(
            p_att, p_att + 128, p_att + 256, p_att + 384, 512,
            nullptr, nullptr, nullptr,
            Wo + (size_t)l * 256 * 128, nullptr, nullptr, nullptr, BIG, 128,
            Wo + (size_t)l * 256 * 128 + 128 * 128,
            p_Wce + (size_t)l * 256 * 128,
            p_Wce + (size_t)l * 256 * 128 + 128 * 128, 128,
            p_cvec + l * 128, p_emb, 128,
            p_p0, p_p1, p_p2, p_p3, 128, 0);

        // combine -> emb, LN2 stats (eps 1e-6)
        combine4_kernel<<<512, 256>>>(p_p0, p_p1, p_p2, p_p3,
                                      p_emb, p_st, 1e-6f);

        // FFN1 (N=512, grid 256), LN-fused, relu
        gemmK<<<dim3(64, 4, 1), 128>>>(
            p_emb, p_emb, p_emb, p_emb, 128,
            p_st, ln2g + l * 128, ln2b + l * 128,
            W1 + (size_t)l * 128 * 512, nullptr, nullptr, nullptr, BIG, 512,
            nullptr, nullptr, nullptr, 0,
            b1 + l * 512, nullptr, 0,
            p_mid, nullptr, nullptr, nullptr, 512, 1);

        // FFN2 split-K=4: mid slices @ W2 slices; z0 adds b2 + emb residual
        gemmK<<<dim3(64, 1, 4), 128>>>(
            p_mid, p_mid + 128, p_mid + 256, p_mid + 384, 512,
            nullptr, nullptr, nullptr,
            W2 + (size_t)l * 512 * 128, nullptr, nullptr, nullptr, BIG, 128,
            W2 + (size_t)l * 512 * 128 + 128 * 128,
            W2 + (size_t)l * 512 * 128 + 256 * 128,
            W2 + (size_t)l * 512 * 128 + 384 * 128, 128,
            b2 + l * 128, p_emb, 128,
            p_p0, p_p1, p_p2, p_p3, 128, 0);

        prev2 = p_p2; prev3 = p_p3;
    }

    mean4_kernel<<<64, 128>>>(p_p0, p_p1, p_p2, p_p3, out);
}

// round 7
// speedup vs baseline: 2.5219x; 1.0618x over previous
#include <cuda_runtime.h>
#include <math.h>
#include <stdint.h>

// ---------------------------------------------------------------------------
// TGAN: 2-layer graph transformer with edge-bias attention.
// B=64, N=64, D=128, NH=2 (d_k=128), L=2.
//   bias = edge@We + be never materialized (folded into weights).
//   gemmK2: 256thr, BM64/BN128, 8x4/thread, f32x2 FFMA2, A-broadcast LDS,
//           cp.async double-buffered W, LN fused into A loads.
//   attn5: both heads per block; edge row-block read once (L1 reuse for ce).
// ---------------------------------------------------------------------------

#define Ll 2
#define ROWS 4096

typedef unsigned long long ull;

// ------------------------- scratch (device globals) ------------------------
__device__ float g_emb [ROWS*128];
__device__ float g_p0  [ROWS*128];
__device__ float g_p1  [ROWS*128];
__device__ float g_p2  [ROWS*128];
__device__ float g_p3  [ROWS*128];
__device__ float g_zero[ROWS*128];      // never written: stays zero
__device__ float g_qkv [ROWS*1024];     // [q(256)|k(256)|v(256)|qe(256)]
__device__ float g_att [ROWS*512];      // [emb1cat(256)|cecat(256)]
__device__ float g_mid [ROWS*512];
__device__ float g_stats[ROWS*2];
__device__ float g_Wqe [Ll*128*256];
__device__ float g_Wce [Ll*256*128];
__device__ float g_cvec[Ll*128];
__device__ unsigned g_pf[64];

// ------------------------- helpers -----------------------------------------
__device__ __forceinline__ ull ffma2(ull a, ull b, ull c) {
    ull d;
    asm("fma.rn.f32x2 %0, %1, %2, %3;" : "=l"(d) : "l"(a), "l"(b), "l"(c));
    return d;
}
__device__ __forceinline__ ull bcast2(float x) {
    ull d;
    asm("mov.b64 %0, {%1, %1};" : "=l"(d) : "r"(__float_as_uint(x)));
    return d;
}
__device__ __forceinline__ void unpack2(ull v, float& lo, float& hi) {
    unsigned a, b;
    asm("mov.b64 {%0, %1}, %2;" : "=r"(a), "=r"(b) : "l"(v));
    lo = __uint_as_float(a); hi = __uint_as_float(b);
}
__device__ __forceinline__ bool mask_at(const void* m, int idx, int mode) {
    if (mode == 0) return ((const int*)m)[idx] != 0;
    if (mode == 1) return ((const float*)m)[idx] != 0.0f;
    return ((const unsigned char*)m)[idx] != 0;
}

// ------------------------- prep (one launch, 577 blocks) --------------------
__global__ __launch_bounds__(256) void prep_kernel(
    const unsigned* __restrict__ mask,
    const float* __restrict__ Wq, const float* __restrict__ We,
    const float* __restrict__ Wo, const float* __restrict__ be,
    const float* __restrict__ bo)
{
    const int bid = blockIdx.x, t = threadIdx.x;
    if (bid < 64) {
        __shared__ unsigned sfl;
        if (t == 0) sfl = 0;
        __syncthreads();
        unsigned f = 0;
        for (int p = bid * 1024 + t; p < (bid + 1) * 1024; p += 256) {
            unsigned w = mask[p];
            if (w > 1u) f |= 1u;
            if (w != 0u && w != 0x3F800000u) f |= 2u;
        }
        if (f) atomicOr(&sfl, f);
        __syncthreads();
        if (t == 0) g_pf[bid] = sfl;
    } else if (bid < 320) {
        int u = bid - 64, l = u >> 7, k = u & 127;
        __shared__ float wqrow[256];
        wqrow[t] = Wq[((size_t)l * 128 + k) * 256 + t];
        __syncthreads();
        int h = t >> 7, e = t & 127;
        const float* we = We + (size_t)l * 16384 + e * 128;
        const float* wq = wqrow + h * 128;
        float s = 0.0f;
        #pragma unroll 8
        for (int d = 0; d < 128; d++) s += wq[d] * we[d];
        g_Wqe[((size_t)l * 128 + k) * 256 + t] = s;
    } else if (bid < 576) {
        int u = bid - 320, l = u >> 7, hp = (u & 127) * 2;
        __shared__ float weS[2][128];
        {
            int r = t >> 7, d = t & 127, he = hp + r, e = he & 127;
            weS[r][d] = We[(size_t)l * 16384 + e * 128 + d];
        }
        __syncthreads();
        int half = t >> 7, n = t & 127;
        int he = hp + half, h = he >> 7;
        const float* wo = Wo + (size_t)l * 32768 + (size_t)h * 128 * 128;
        float s = 0.0f;
        #pragma unroll 8
        for (int d = 0; d < 128; d++) s += weS[half][d] * wo[d * 128 + n];
        g_Wce[((size_t)l * 256 + he) * 128 + n] = s;
    } else {
        int l = t >> 7, n = t & 127;
        const float* wo = Wo + (size_t)l * 32768;
        const float* bel = be + l * 128;
        float s = bo[l * 128 + n];
        #pragma unroll 8
        for (int d = 0; d < 128; d++)
            s += bel[d] * (wo[d * 128 + n] + wo[(128 + d) * 128 + n]);
        g_cvec[l * 128 + n] = s;
    }
}

// ------------------------- combine 4 partials + LN stats --------------------
__global__ __launch_bounds__(256) void combine4_kernel(
    const float* __restrict__ p0, const float* __restrict__ p1,
    const float* __restrict__ p2, const float* __restrict__ p3,
    float* __restrict__ emb, float* __restrict__ st, float eps)
{
    int row = blockIdx.x * 8 + (threadIdx.x >> 5);
    int lane = threadIdx.x & 31;
    float4 a = ((const float4*)(p0 + (size_t)row * 128))[lane];
    float4 b = ((const float4*)(p1 + (size_t)row * 128))[lane];
    float4 c = ((const float4*)(p2 + (size_t)row * 128))[lane];
    float4 d = ((const float4*)(p3 + (size_t)row * 128))[lane];
    float4 v;
    v.x = (a.x + b.x) + (c.x + d.x); v.y = (a.y + b.y) + (c.y + d.y);
    v.z = (a.z + b.z) + (c.z + d.z); v.w = (a.w + b.w) + (c.w + d.w);
    ((float4*)(emb + (size_t)row * 128))[lane] = v;
    float s = v.x + v.y + v.z + v.w;
    float q = v.x*v.x + v.y*v.y + v.z*v.z + v.w*v.w;
    #pragma unroll
    for (int o = 16; o; o >>= 1) {
        s += __shfl_xor_sync(0xffffffffu, s, o);
        q += __shfl_xor_sync(0xffffffffu, q, o);
    }
    if (lane == 0) {
        float mu = s * (1.0f / 128.0f);
        float var = q * (1.0f / 128.0f) - mu * mu;
        st[row * 2] = mu;
        st[row * 2 + 1] = rsqrtf(var + eps);
    }
}

// ------------------------- gemmK2: BM=64 BN=128, 256 threads, 8x4 -----------
// K must be 128. z==0: n-select W among Wp0..3 (wspan), bias/res allowed.
// z>0: A/W/C from z-indexed args (split-K partials).
__global__ __launch_bounds__(256, 3) void gemmK2(
    const float* __restrict__ A0, const float* __restrict__ A1,
    const float* __restrict__ A2, const float* __restrict__ A3, int sA,
    const float* __restrict__ lnst, const float* __restrict__ lng,
    const float* __restrict__ lnb,
    const float* __restrict__ Wp0, const float* __restrict__ Wp1,
    const float* __restrict__ Wp2, const float* __restrict__ Wp3,
    int wspan, int sW,
    const float* __restrict__ Wz1, const float* __restrict__ Wz2,
    const float* __restrict__ Wz3, int sWz,
    const float* __restrict__ bias, const float* __restrict__ res, int sR,
    float* __restrict__ C0, float* __restrict__ C1,
    float* __restrict__ C2, float* __restrict__ C3, int sC, int relu)
{
    __shared__ __align__(16) float AsT[2][16][68];
    __shared__ __align__(16) float Wsm[2][16][128];

    const int m0 = blockIdx.x * 64, n0 = blockIdx.y * 128;
    const int z = blockIdx.z;
    const int t = threadIdx.x;
    const int lm = t >> 2, lk = (t & 3) * 4;       // A loader: 64 rows x 16 k
    const int wkr = t >> 4, wnc = (t & 15) * 8;    // W loader (2x cp.async 16B)
    const int tmi = t >> 5, tni = t & 31;          // compute: m=tmi*8, n=tni*4

    const float *A, *W; float* C;
    const float *biasx, *resx;
    int sWx;
    if (z == 0) {
        A = A0; C = C0;
        int sel = n0 / wspan;
        W = ((sel == 0) ? Wp0 : (sel == 1) ? Wp1 : (sel == 2) ? Wp2 : Wp3)
            + (n0 - sel * wspan);
        sWx = sW; biasx = bias; resx = res;
    } else {
        A = (z == 1) ? A1 : (z == 2) ? A2 : A3;
        W = ((z == 1) ? Wz1 : (z == 2) ? Wz2 : Wz3) + n0;
        C = (z == 1) ? C1 : (z == 2) ? C2 : C3;
        sWx = sWz; biasx = nullptr; resx = nullptr;
    }

    const bool doLN = (lnst != nullptr);
    float2 st = make_float2(0.0f, 1.0f);
    if (doLN) st = *(const float2*)(lnst + (size_t)(m0 + lm) * 2);

    const uint32_t wsm_base = (uint32_t)__cvta_generic_to_shared(&Wsm[0][0][0]);

    auto issueW = [&](int k0, int buf) {
        const float* src = W + (size_t)(k0 + wkr) * sWx + wnc;
        uint32_t dst = wsm_base + (uint32_t)(((buf * 16 + wkr) * 128 + wnc) * 4);
        asm volatile("cp.async.cg.shared.global [%0], [%1], 16;"
                     :: "r"(dst), "l"(src));
        asm volatile("cp.async.cg.shared.global [%0], [%1], 16;"
                     :: "r"(dst + 16), "l"(src + 4));
        asm volatile("cp.async.commit_group;");
    };
    auto loadA = [&](int k0) -> float4 {
        float4 v = *(const float4*)(A + (size_t)(m0 + lm) * sA + k0 + lk);
        if (doLN) {
            float4 g4 = *(const float4*)(lng + k0 + lk);
            float4 b4 = *(const float4*)(lnb + k0 + lk);
            v.x = (v.x - st.x) * st.y * g4.x + b4.x;
            v.y = (v.y - st.x) * st.y * g4.y + b4.y;
            v.z = (v.z - st.x) * st.y * g4.z + b4.z;
            v.w = (v.w - st.x) * st.y * g4.w + b4.w;
        }
        return v;
    };

    ull acc[4][4];
    #pragma unroll
    for (int p = 0; p < 4; p++)
        #pragma unroll
        for (int j = 0; j < 4; j++) acc[p][j] = 0ull;

    issueW(0, 0);
    float4 a0 = loadA(0);

    const int S = 8;  // K = 128
    #pragma unroll 2
    for (int s = 0; s < S; s++) {
        const int buf = s & 1;
        AsT[buf][lk+0][lm] = a0.x; AsT[buf][lk+1][lm] = a0.y;
        AsT[buf][lk+2][lm] = a0.z; AsT[buf][lk+3][lm] = a0.w;
        asm volatile("cp.async.wait_group 0;");
        __syncthreads();
        if (s + 1 < S) {
            issueW((s + 1) << 4, buf ^ 1);
            a0 = loadA((s + 1) << 4);
        }
        #pragma unroll
        for (int kk = 0; kk < 16; kk++) {
            ulonglong2 A01 = *(const ulonglong2*)&AsT[buf][kk][tmi * 8];
            ulonglong2 A23 = *(const ulonglong2*)&AsT[buf][kk][tmi * 8 + 4];
            float4 w = *(const float4*)&Wsm[buf][kk][tni * 4];
            ull b0 = bcast2(w.x), b1 = bcast2(w.y);
            ull b2 = bcast2(w.z), b3 = bcast2(w.w);
            acc[0][0] = ffma2(A01.x, b0, acc[0][0]);
            acc[0][1] = ffma2(A01.x, b1, acc[0][1]);
            acc[0][2] = ffma2(A01.x, b2, acc[0][2]);
            acc[0][3] = ffma2(A01.x, b3, acc[0][3]);
            acc[1][0] = ffma2(A01.y, b0, acc[1][0]);
            acc[1][1] = ffma2(A01.y, b1, acc[1][1]);
            acc[1][2] = ffma2(A01.y, b2, acc[1][2]);
            acc[1][3] = ffma2(A01.y, b3, acc[1][3]);
            acc[2][0] = ffma2(A23.x, b0, acc[2][0]);
            acc[2][1] = ffma2(A23.x, b1, acc[2][1]);
            acc[2][2] = ffma2(A23.x, b2, acc[2][2]);
            acc[2][3] = ffma2(A23.x, b3, acc[2][3]);
            acc[3][0] = ffma2(A23.y, b0, acc[3][0]);
            acc[3][1] = ffma2(A23.y, b1, acc[3][1]);
            acc[3][2] = ffma2(A23.y, b2, acc[3][2]);
            acc[3][3] = ffma2(A23.y, b3, acc[3][3]);
        }
        __syncthreads();
    }

    float4 bv = make_float4(0.f, 0.f, 0.f, 0.f);
    if (biasx) bv = *(const float4*)&biasx[n0 + tni * 4];
    #pragma unroll
    for (int p = 0; p < 4; p++) {
        float lo[4], hi[4];
        #pragma unroll
        for (int j = 0; j < 4; j++) unpack2(acc[p][j], lo[j], hi[j]);
        #pragma unroll
        for (int r = 0; r < 2; r++) {
            float* o = r ? hi : lo;
            size_t row = (size_t)(m0 + tmi * 8 + p * 2 + r);
            float4 ov;
            ov.x = o[0] + bv.x; ov.y = o[1] + bv.y;
            ov.z = o[2] + bv.z; ov.w = o[3] + bv.w;
            if (resx) {
                float4 r4 = *(const float4*)&resx[row * sR + n0 + tni * 4];
                ov.x += r4.x; ov.y += r4.y; ov.z += r4.z; ov.w += r4.w;
            }
            if (relu) {
                ov.x = fmaxf(ov.x, 0.f); ov.y = fmaxf(ov.y, 0.f);
                ov.z = fmaxf(ov.z, 0.f); ov.w = fmaxf(ov.w, 0.f);
            }
            *(float4*)&C[row * sC + n0 + tni * 4] = ov;
        }
    }
}

// ------------------------- fused attention v5 (both heads) ------------------
// Block = (b, 8-row tile). Score computes both heads per single edge read;
// ce phase re-reads the row-block while L1-resident. smem ~84KB.
#define TI 8
#define ATTN_SMEM ((16384 + TI*256*2 + 128 + 128 + 128 + 16 + 16 + 4) * 4)

__global__ __launch_bounds__(256) void attn5_kernel(
    const float* __restrict__ qkv, const float* __restrict__ edge,
    const float* __restrict__ be, const void* __restrict__ mask,
    float* __restrict__ aout, float* __restrict__ att)
{
    extern __shared__ float sm[];
    float* vs   = sm;              // [64][256] both heads
    float* qs   = vs + 16384;      // [TI][256]
    float* qes  = qs + TI*256;     // [TI][256]
    float* sraw = qes + TI*256;    // [128] (h*64+j)
    float* sa   = sraw + 128;      // [128]
    float* bes  = sa + 128;        // [128]
    float* red  = bes + 128;       // [16]
    float* qbe  = red + 16;        // [16] (h*8+ii)
    unsigned* s_or = (unsigned*)(qbe + 16);

    const int b = blockIdx.x, it0 = blockIdx.y * TI, t = threadIdx.x;
    const int w = t >> 5, lane = t & 31;
    const float4* qkv4 = (const float4*)qkv;
    const float4* edge4 = (const float4*)edge;

    // V both heads
    #pragma unroll
    for (int p = t; p < 4096; p += 256) {
        int j = p >> 6, c = p & 63;
        ((float4*)vs)[p] = qkv4[(size_t)(b * 64 + j) * 256 + 128 + c];
    }
    // Q / QE rows for tile
    #pragma unroll
    for (int p = t; p < TI * 64; p += 256) {
        int r = p >> 6, c = p & 63;
        ((float4*)qs)[p]  = qkv4[(size_t)(b * 64 + it0 + r) * 256 + c];
        ((float4*)qes)[p] = qkv4[(size_t)(b * 64 + it0 + r) * 256 + 192 + c];
    }
    if (t < 128) bes[t] = be[t];
    if (t < 64) {
        unsigned f = g_pf[t];
        #pragma unroll
        for (int o = 16; o; o >>= 1) f |= __shfl_xor_sync(0xffffffffu, f, o);
        if (lane == 0) s_or[w] = f;
    }
    __syncthreads();

    const unsigned fl = s_or[0] | s_or[1];
    const int mode = (!(fl & 1u)) ? 0 : ((!(fl & 2u)) ? 1 : 2);

    // qbe[h*8+ii] (16 tasks over 8 warps)
    #pragma unroll
    for (int r = 0; r < 2; r++) {
        int task = w * 2 + r;
        int h = task >> 3, ii = task & 7;
        const float* qrow = qs + ii * 256 + h * 128;
        float s = 0.0f;
        #pragma unroll
        for (int c = 0; c < 4; c++) s += qrow[lane + 32*c] * bes[lane + 32*c];
        #pragma unroll
        for (int o = 16; o; o >>= 1) s += __shfl_xor_sync(0xffffffffu, s, o);
        if (lane == 0) qbe[task] = s;
    }

    const float invT = 0.0883883476483184405f;  // 1/sqrt(128)
    const float4* qs4 = (const float4*)qs;
    const float4* qes4 = (const float4*)qes;

    for (int ii = 0; ii < TI; ii++) {
        const int i = it0 + ii;
        __syncthreads();

        // ---- scores both heads: warp w handles j = w*8..w*8+7 ----
        {
            float4 q0 = qs4[ii*64 + lane],      q1 = qs4[ii*64 + 32 + lane];
            float4 g0 = qes4[ii*64 + lane],     g1 = qes4[ii*64 + 32 + lane];
            size_t erow0 = (size_t)(b * 64 + i) * 64;
            float s0[8], s1[8];
            #pragma unroll
            for (int r = 0; r < 8; r++) {
                int j = w * 8 + r;
                float4 ee = edge4[(erow0 + j) * 32 + lane];
                float4 ka = qkv4[(size_t)(b*64 + j) * 256 + 64 + lane];
                float4 kb = qkv4[(size_t)(b*64 + j) * 256 + 96 + lane];
                s0[r] = q0.x*ka.x + q0.y*ka.y + q0.z*ka.z + q0.w*ka.w
                      + g0.x*ee.x + g0.y*ee.y + g0.z*ee.z + g0.w*ee.w;
                s1[r] = q1.x*kb.x + q1.y*kb.y + q1.z*kb.z + q1.w*kb.w
                      + g1.x*ee.x + g1.y*ee.y + g1.z*ee.z + g1.w*ee.w;
            }
            #pragma unroll
            for (int o = 16; o; o >>= 1) {
                #pragma unroll
                for (int r = 0; r < 8; r++) {
                    s0[r] += __shfl_xor_sync(0xffffffffu, s0[r], o);
                    s1[r] += __shfl_xor_sync(0xffffffffu, s1[r], o);
                }
            }
            if (lane == 0) {
                #pragma unroll
                for (int r = 0; r < 8; r++) {
                    sraw[w * 8 + r]      = s0[r];
                    sraw[64 + w * 8 + r] = s1[r];
                }
            }
        }
        __syncthreads();

        // ---- softmax (threads 0..127 = (h,j)) ----
        int h = (t >> 6) & 1, j = t & 63;
        float sc = 0.0f, ex = 0.0f;
        if (t < 128) {
            sc = (sraw[t] + qbe[h * 8 + ii]) * invT;
            if (mask_at(mask, ((b * 64 + i) << 6) + j, mode)) sc = 1e-10f;
            float m = sc;
            #pragma unroll
            for (int o = 16; o; o >>= 1)
                m = fmaxf(m, __shfl_xor_sync(0xffffffffu, m, o));
            if ((t & 31) == 0) red[t >> 5] = m;
        }
        __syncthreads();
        if (t < 128) {
            float hm = fmaxf(red[h * 2], red[h * 2 + 1]);
            ex = __expf(sc - hm);
            float ws = ex;
            #pragma unroll
            for (int o = 16; o; o >>= 1) ws += __shfl_xor_sync(0xffffffffu, ws, o);
            if ((t & 31) == 0) red[8 + (t >> 5)] = ws;
        }
        __syncthreads();
        if (t < 128) {
            float a = ex / (red[8 + h * 2] + red[8 + h * 2 + 1]);
            sa[t] = a;
            aout[((size_t)(h * 64 + b)) * 4096 + i * 64 + j] = a;
        }
        __syncthreads();

        // ---- emb1 = attn@V (smem), ce = attn@edge (global, L1-hot) ----
        {
            int h2 = t >> 7, dd = t & 127;
            const float* arow = sa + h2 * 64;
            const float* vcol = vs + h2 * 128 + dd;
            const float* ecol = edge + (size_t)(b * 64 + i) * 8192 + dd;
            float e1 = 0.0f, ec = 0.0f;
            #pragma unroll 8
            for (int jj = 0; jj < 64; jj++) {
                float a = arow[jj];
                e1 += a * vcol[jj * 256];
                ec += a * ecol[jj * 128];
            }
            size_t row = (size_t)(b * 64 + i);
            att[row * 512 + h2 * 128 + dd]       = e1;
            att[row * 512 + 256 + h2 * 128 + dd] = ec;
        }
    }
}

// ------------------------- final mean over 4 partials -----------------------
__global__ __launch_bounds__(128) void mean4_kernel(
    const float* __restrict__ p0, const float* __restrict__ p1,
    const float* __restrict__ p2, const float* __restrict__ p3,
    float* __restrict__ out)
{
    int b = blockIdx.x, d = threadIdx.x;
    float s = 0.0f;
    #pragma unroll 4
    for (int n = 0; n < 64; n++) {
        size_t idx = ((size_t)b * 64 + n) * 128 + d;
        s += (p0[idx] + p1[idx]) + (p2[idx] + p3[idx]);
    }
    out[b * 128 + d] = s * (1.0f / 64.0f);
}

// ---------------------------------------------------------------------------
extern "C" void kernel_launch(void* const* d_in, const int* in_sizes, int n_in,
                              void* d_out, int out_size)
{
    int mi = (in_sizes[3] == 262144) ? 3 : (n_in - 1);
    int wb = (mi == 3) ? 4 : 3;

    const float* node = (const float*)d_in[0];
    const float* stpe = (const float*)d_in[1];
    const float* edge = (const float*)d_in[2];
    const void*  mask = d_in[mi];
    const float* Wn   = (const float*)d_in[wb + 0];
    const float* bn   = (const float*)d_in[wb + 1];
    const float* We   = (const float*)d_in[wb + 2];
    const float* be   = (const float*)d_in[wb + 3];
    const float* ln1g = (const float*)d_in[wb + 4];
    const float* ln1b = (const float*)d_in[wb + 5];
    const float* Wq   = (const float*)d_in[wb + 6];
    const float* Wk   = (const float*)d_in[wb + 7];
    const float* Wv   = (const float*)d_in[wb + 8];
    const float* Wo   = (const float*)d_in[wb + 9];
    const float* bo   = (const float*)d_in[wb + 10];
    const float* ln2g = (const float*)d_in[wb + 11];
    const float* ln2b = (const float*)d_in[wb + 12];
    const float* W1   = (const float*)d_in[wb + 13];
    const float* b1   = (const float*)d_in[wb + 14];
    const float* W2   = (const float*)d_in[wb + 15];
    const float* b2   = (const float*)d_in[wb + 16];
    float* out = (float*)d_out;

    cudaFuncSetAttribute(attn5_kernel,
                         cudaFuncAttributeMaxDynamicSharedMemorySize, ATTN_SMEM);

    float *p_emb, *p_p0, *p_p1, *p_p2, *p_p3, *p_zero, *p_qkv, *p_att,
          *p_mid, *p_st, *p_Wqe, *p_Wce, *p_cvec;
    cudaGetSymbolAddress((void**)&p_emb,  g_emb);
    cudaGetSymbolAddress((void**)&p_p0,   g_p0);
    cudaGetSymbolAddress((void**)&p_p1,   g_p1);
    cudaGetSymbolAddress((void**)&p_p2,   g_p2);
    cudaGetSymbolAddress((void**)&p_p3,   g_p3);
    cudaGetSymbolAddress((void**)&p_zero, g_zero);
    cudaGetSymbolAddress((void**)&p_qkv,  g_qkv);
    cudaGetSymbolAddress((void**)&p_att,  g_att);
    cudaGetSymbolAddress((void**)&p_mid,  g_mid);
    cudaGetSymbolAddress((void**)&p_st,   g_stats);
    cudaGetSymbolAddress((void**)&p_Wqe,  g_Wqe);
    cudaGetSymbolAddress((void**)&p_Wce,  g_Wce);
    cudaGetSymbolAddress((void**)&p_cvec, g_cvec);

    const int BIG = 1 << 20;

    prep_kernel<<<577, 256>>>((const unsigned*)mask, Wq, We, Wo, be, bo);

    // emb partials: z0 = node@Wn[0:128]+bn -> p0, z1 = stpe@Wn[128:256] -> p1
    gemmK2<<<dim3(64, 1, 2), 256>>>(
        node, stpe, stpe, stpe, 128,
        nullptr, nullptr, nullptr,
        Wn, Wn, Wn, Wn, BIG, 128,
        Wn + 128 * 128, Wn + 128 * 128, Wn + 128 * 128, 128,
        bn, nullptr, 0,
        p_p0, p_p1, p_p1, p_p1, 128, 0);

    const float* prev2 = p_zero;
    const float* prev3 = p_zero;

    for (int l = 0; l < Ll; l++) {
        combine4_kernel<<<512, 256>>>(p_p0, p_p1, prev2, prev3,
                                      p_emb, p_st, 1e-5f);

        // fused QKV+QE projection (N=1024, grid 512)
        gemmK2<<<dim3(64, 8, 1), 256>>>(
            p_emb, p_emb, p_emb, p_emb, 128,
            p_st, ln1g + l * 128, ln1b + l * 128,
            Wq + (size_t)l * 128 * 256, Wk + (size_t)l * 128 * 256,
            Wv + (size_t)l * 128 * 256, p_Wqe + (size_t)l * 128 * 256,
            256, 256,
            nullptr, nullptr, nullptr, 0,
            nullptr, nullptr, 0,
            p_qkv, nullptr, nullptr, nullptr, 1024, 0);

        // attention (both heads per block, grid 512)
        attn5_kernel<<<dim3(64, 64 / TI), 256, ATTN_SMEM>>>(
            p_qkv, edge, be + l * 128, mask,
            out + 8192 + (size_t)l * 2 * 64 * 4096, p_att);

        // output proj split-K=4
        gemmK2<<<dim3(64, 1, 4), 256>>>(
            p_att, p_att + 128, p_att + 256, p_att + 384, 512,
            nullptr, nullptr, nullptr,
            Wo + (size_t)l * 256 * 128, nullptr, nullptr, nullptr, BIG, 128,
            Wo + (size_t)l * 256 * 128 + 128 * 128,
            p_Wce + (size_t)l * 256 * 128,
            p_Wce + (size_t)l * 256 * 128 + 128 * 128, 128,
            p_cvec + l * 128, p_emb, 128,
            p_p0, p_p1, p_p2, p_p3, 128, 0);

        combine4_kernel<<<512, 256>>>(p_p0, p_p1, p_p2, p_p3,
                                      p_emb, p_st, 1e-6f);

        // FFN1 (N=512, grid 256), LN-fused, relu
        gemmK2<<<dim3(64, 4, 1), 256>>>(
            p_emb, p_emb, p_emb, p_emb, 128,
            p_st, ln2g + l * 128, ln2b + l * 128,
            W1 + (size_t)l * 128 * 512, nullptr, nullptr, nullptr, BIG, 512,
            nullptr, nullptr, nullptr, 0,
            b1 + l * 512, nullptr, 0,
            p_mid, nullptr, nullptr, nullptr, 512, 1);

        // FFN2 split-K=4
        gemmK2<<<dim3(64, 1, 4), 256>>>(
            p_mid, p_mid + 128, p_mid + 256, p_mid + 384, 512,
            nullptr, nullptr, nullptr,
            W2 + (size_t)l * 512 * 128, nullptr, nullptr, nullptr, BIG, 128,
            W2 + (size_t)l * 512 * 128 + 128 * 128,
            W2 + (size_t)l * 512 * 128 + 256 * 128,
            W2 + (size_t)l * 512 * 128 + 384 * 128, 128,
            b2 + l * 128, p_emb, 128,
            p_p0, p_p1, p_p2, p_p3, 128, 0);

        prev2 = p_p2; prev3 = p_p3;
    }

    mean4_kernel<<<64, 128>>>(p_p0, p_p1, p_p2, p_p3, out);
}